// round 12
// baseline (speedup 1.0000x reference)
#include <cuda_runtime.h>

#define BATCH 8
typedef unsigned long long u64;

__device__ __align__(16) unsigned char g_qw[36595968];
__device__ __align__(16) unsigned char g_qa[262144];
__device__ __align__(16) float g_fbuf[524288];
// max bits: 0..7 = |w0..7|, 8 = |x|, 9..13 = conv0..4 out, 14/15 = fc5/6 out
__device__ int g_maxi[16];

#define W0OFF 0
#define W1OFF 2304
#define W2OFF 149760
#define W3OFF 1034496
#define W4OFF 2214144
#define W5OFF 3000576
#define W6OFF 19777792
#define W7OFF 36555008

__device__ __forceinline__ float slot_scale(int s) {
    return fmaxf(__fdiv_rn(__int_as_float(g_maxi[s]), 7.0f), 1e-8f);
}
__device__ __forceinline__ unsigned int quant_idx(float x, float s) {
    float q = rintf(__fdiv_rn(x, s));  // half-even, exact div
    q = fminf(fmaxf(q, -8.0f), 7.0f);
    return (unsigned int)((int)q + 8);
}
__device__ __forceinline__ void kahan(float& s, float& c, float val) {
    float y = __fadd_rn(val, -c);
    float t = __fadd_rn(s, y);
    c = __fadd_rn(__fadd_rn(t, -s), -y);
    s = t;
}
__device__ __forceinline__ u64 pack2(float lo, float hi) {
    u64 v; asm("mov.b64 %0, {%1, %2};" : "=l"(v) : "f"(lo), "f"(hi)); return v;
}
__device__ __forceinline__ void unpack2(u64 v, float& lo, float& hi) {
    asm("mov.b64 {%0, %1}, %2;" : "=f"(lo), "=f"(hi) : "l"(v));
}
__device__ __forceinline__ void kahan2(u64& s, u64& c, u64 val) {
    u64 y, t, d;
    asm("sub.rn.f32x2 %0, %1, %2;" : "=l"(y) : "l"(val), "l"(c));
    asm("add.rn.f32x2 %0, %1, %2;" : "=l"(t) : "l"(s), "l"(y));
    asm("sub.rn.f32x2 %0, %1, %2;" : "=l"(d) : "l"(t), "l"(s));
    asm("sub.rn.f32x2 %0, %1, %2;" : "=l"(c) : "l"(d), "l"(y));
    s = t;
}
#define NEG2(v) ((v) ^ 0x8000000080000000ULL)

__global__ void k_init() { if (threadIdx.x < 16) g_maxi[threadIdx.x] = 0; }

struct AMaxArgs { const float* p[9]; int n[9]; int slot[9]; int b0[10]; };
__global__ void k_absmax_all(AMaxArgs a) {
    int seg = 0;
#pragma unroll
    for (int i = 1; i < 9; i++) if ((int)blockIdx.x >= a.b0[i]) seg = i;
    int lb = blockIdx.x - a.b0[seg], nb = a.b0[seg + 1] - a.b0[seg];
    const float4* p4 = (const float4*)a.p[seg];
    int n4 = a.n[seg] >> 2;
    float m = 0.0f;
    for (int i = lb * 256 + threadIdx.x; i < n4; i += nb * 256) {
        float4 v = p4[i];
        m = fmaxf(m, fmaxf(fmaxf(fabsf(v.x), fabsf(v.y)), fmaxf(fabsf(v.z), fabsf(v.w))));
    }
#pragma unroll
    for (int o = 16; o; o >>= 1) m = fmaxf(m, __shfl_xor_sync(0xffffffffu, m, o));
    if ((threadIdx.x & 31) == 0) atomicMax(&g_maxi[a.slot[seg]], __float_as_int(m));
}

struct QWCArgs { const float* w[5]; };
__global__ void k_qw_conv(QWCArgs a) {
    const int OA[5] = {64, 192, 384, 256, 256}, CA[5] = {3, 64, 192, 384, 256};
    const int WO[5] = {W0OFF, W1OFF, W2OFF, W3OFF, W4OFF};
    const int BASE[6] = {0, 576, 37440, 258624, 553536, 750144};
    int idx = blockIdx.x * blockDim.x + threadIdx.x;
    if (idx >= 750144) return;
    int l = 0;
#pragma unroll
    for (int i = 1; i < 5; i++) if (idx >= BASE[i]) l = i;
    int li = idx - BASE[l], O = OA[l], C = CA[l];
    float s = slot_scale(l);
    int o = li % O, ckh = li / O, c = ckh / 3, kh = ckh % 3;
    const float* src = a.w[l] + ((size_t)(o * C + c) * 3 + kh) * 3;
    uchar4 v;
    v.x = (unsigned char)(quant_idx(src[0], s) << 2);
    v.y = (unsigned char)(quant_idx(src[1], s) << 2);
    v.z = (unsigned char)(quant_idx(src[2], s) << 2);
    v.w = 0;
    reinterpret_cast<uchar4*>(g_qw + WO[l])[(size_t)ckh * O + o] = v;
}

struct QWFArgs { const float* w[3]; };
__global__ void k_qw_fc(QWFArgs a) {
    const int OA[3] = {4096, 4096, 10};
    const int WO[3] = {W5OFF, W6OFF, W7OFF};
    const int z = blockIdx.z, F = 4096, O = OA[z];
    __shared__ unsigned char t[128][33];
    float s = slot_scale(5 + z);
    int f0 = blockIdx.x * 128, o0 = blockIdx.y * 32;
    if (o0 >= O) return;
    const float* w = a.w[z];
    for (int i = threadIdx.x; i < 32 * 128; i += blockDim.x) {
        int ol = i >> 7, fl = i & 127, o = o0 + ol;
        unsigned char q = 0;
        if (o < O) q = (unsigned char)(quant_idx(w[(size_t)o * F + f0 + fl], s) << 2);
        t[fl][ol] = q;
    }
    __syncthreads();
    for (int i = threadIdx.x; i < 32 * 32; i += blockDim.x) {
        int f4l = i >> 5, ol = i & 31, o = o0 + ol;
        if (o >= O) continue;
        uchar4 v;
        v.x = t[f4l * 4 + 0][ol]; v.y = t[f4l * 4 + 1][ol];
        v.z = t[f4l * 4 + 2][ol]; v.w = t[f4l * 4 + 3][ol];
        reinterpret_cast<uchar4*>(g_qw + WO[z])[(size_t)(f0 / 4 + f4l) * O + o] = v;
    }
}

__global__ void k_quant_act(const float* in, int C, int H, int W, int slot) {
    const float* src = in ? in : g_fbuf;
    int n = BATCH * C * H * W;
    float s = slot_scale(slot);
    for (int idx = blockIdx.x * blockDim.x + threadIdx.x; idx < n; idx += gridDim.x * blockDim.x) {
        int w = idx % W, t = idx / W, h = t % H; t /= H;
        int c = t % C, b = t / C;
        g_qa[((b * H + h) * C + c) * W + w] = (unsigned char)quant_idx(src[idx], s);
    }
}

__global__ void k_pool_quant(int C, int H, int W, int slot) {
    int H2 = H >> 1, W2 = W >> 1, n = BATCH * C * H2 * W2;
    float s = slot_scale(slot);
    for (int idx = blockIdx.x * blockDim.x + threadIdx.x; idx < n; idx += gridDim.x * blockDim.x) {
        int w = idx % W2, t = idx / W2, h = t % H2; t /= H2;
        int c = t % C, b = t / C;
        const float* p = g_fbuf + (((size_t)(b * C + c) * H + 2 * h) * W + 2 * w);
        float v = fmaxf(fmaxf(p[0], p[1]), fmaxf(p[W], p[W + 1]));
        g_qa[((b * H2 + h) * C + c) * W2 + w] = (unsigned char)quant_idx(v, s);
    }
}

__global__ void k_pool_quant_fc(int slot) {
    int n = BATCH * 4096;
    float s = slot_scale(slot);
    for (int idx = blockIdx.x * blockDim.x + threadIdx.x; idx < n; idx += gridDim.x * blockDim.x) {
        int w = idx % 4, h = (idx / 4) % 4, c = (idx / 16) % 256, b = idx / 4096;
        const float* p = g_fbuf + (((size_t)(b * 256 + c) * 8 + 2 * h) * 8 + 2 * w);
        float v = fmaxf(fmaxf(p[0], p[1]), fmaxf(p[8], p[9]));
        g_qa[b * 4096 + (c * 16 + h * 4 + w)] = (unsigned char)quant_idx(v, s);
    }
}

__global__ void k_quant_act_fc(int slot) {
    float s = slot_scale(slot);
    int idx = blockIdx.x * blockDim.x + threadIdx.x;
    if (idx < BATCH * 4096) g_qa[idx] = (unsigned char)quant_idx(g_fbuf[idx], s);
}

// ------- LUT conv: 64 o-lanes x NC chunks; QUANT fuses x-quant (conv0 only) -------
template <int C, int O, int H, int W, int WT, int NC, bool QUANT>
__global__ void __launch_bounds__(64 * NC) k_conv(const float* __restrict__ lut,
                                                  const float* __restrict__ bias,
                                                  const float* __restrict__ fsrc,
                                                  int woff, int aslot, int wslot, int oslot) {
    constexpr int TW = WT + 4;   // padded row; only WT+2 entries used
    constexpr int WP = WT / 2;   // packed chains
    __shared__ float slut[256];
    __shared__ __align__(16) unsigned short sia[3 * C * TW];
    __shared__ u64 sred[(NC > 1 ? (NC - 1) * 64 * (2 * WP + 1) : 1)];
    const int lane_o = threadIdx.x;  // 0..63
    const int cc = threadIdx.y;      // 0..NC-1
    const int tid = lane_o + 64 * cc;
    constexpr int NT = 64 * NC;
    const int o = blockIdx.x * 64 + lane_o;
    const int w0 = blockIdx.y * WT;
    const int b = blockIdx.z / H, h = blockIdx.z % H;

    for (int i = tid; i < 256; i += NT) slut[i] = lut[i];
    {
        float sa = QUANT ? slot_scale(aslot) : 0.0f;
        for (int i = tid; i < 3 * C * TW; i += NT) {
            int r = i / (C * TW), rem = i - r * C * TW, c = rem / TW, ww = rem - c * TW;
            int gh = h + r - 1, gw = w0 + ww - 1;
            unsigned int v = 8;  // quantized-zero level: padding goes through the LUT
            if (ww < WT + 2 && (unsigned)gh < (unsigned)H && (unsigned)gw < (unsigned)W) {
                if (QUANT)
                    v = quant_idx(fsrc[((size_t)(b * C + c) * H + gh) * W + gw], sa);
                else
                    v = g_qa[((b * H + gh) * C + c) * W + gw];
            }
            sia[i] = (unsigned short)(v << 6);
        }
    }
    __syncthreads();

    u64 acc2[WP], cmp2[WP];
#pragma unroll
    for (int i = 0; i < WP; ++i) { acc2[i] = 0ULL; cmp2[i] = 0ULL; }
    const uchar4* wq = reinterpret_cast<const uchar4*>(g_qw + woff) + o;
    const char* lb = reinterpret_cast<const char*>(slut);
    constexpr int CS = C / NC;
    const int cbeg = cc * CS;

    for (int c = cbeg; c < cbeg + CS; ++c) {
#pragma unroll
        for (int kh = 0; kh < 3; ++kh) {
            uchar4 wv = wq[(c * 3 + kh) * O];
            const unsigned short* row = &sia[(kh * C + c) * TW];
            unsigned int rv[WT + 2];
#pragma unroll
            for (int i = 0; i < WT + 2; ++i) rv[i] = row[i];
            unsigned int woffs[3] = {wv.x, wv.y, wv.z};
#pragma unroll
            for (int kw = 0; kw < 3; ++kw)
#pragma unroll
                for (int wp = 0; wp < WP; ++wp) {
                    float v0 = *reinterpret_cast<const float*>(lb + (rv[2 * wp + kw] + woffs[kw]));
                    float v1 = *reinterpret_cast<const float*>(lb + (rv[2 * wp + 1 + kw] + woffs[kw]));
                    kahan2(acc2[wp], cmp2[wp], pack2(v0, v1));
                }
        }
    }

    if (NC > 1) {
        constexpr int STR = 2 * WP + 1;
        if (cc > 0) {
            u64* dp = &sred[((cc - 1) * 64 + lane_o) * STR];
#pragma unroll
            for (int i = 0; i < WP; ++i) { dp[i] = acc2[i]; dp[WP + i] = cmp2[i]; }
        }
        __syncthreads();
        if (cc == 0) {
#pragma unroll
            for (int i = 0; i < NC - 1; ++i) {
                const u64* sp = &sred[(i * 64 + lane_o) * STR];
#pragma unroll
                for (int wp = 0; wp < WP; ++wp) {
                    kahan2(acc2[wp], cmp2[wp], sp[wp]);
                    kahan2(acc2[wp], cmp2[wp], NEG2(sp[WP + wp]));
                }
            }
        }
    }

    if (cc == 0) {
        float sc = __fmul_rn(slot_scale(aslot), slot_scale(wslot));
        float bv = bias[o], m = 0.0f;
#pragma unroll
        for (int wp = 0; wp < WP; ++wp) {
            float a0, a1;
            unpack2(acc2[wp], a0, a1);
            float v0 = fmaxf(__fadd_rn(__fmul_rn(a0, sc), bv), 0.0f);
            float v1 = fmaxf(__fadd_rn(__fmul_rn(a1, sc), bv), 0.0f);
            size_t base = ((size_t)(b * O + o) * H + h) * W + w0 + 2 * wp;
            g_fbuf[base] = v0;
            g_fbuf[base + 1] = v1;
            m = fmaxf(m, fmaxf(v0, v1));
        }
#pragma unroll
        for (int off = 16; off; off >>= 1) m = fmaxf(m, __shfl_xor_sync(0xffffffffu, m, off));
        if ((lane_o & 31) == 0) atomicMax(&g_maxi[oslot], __float_as_int(m));
    }
}

// ------- LUT fc: OT o-lanes x NC f-chunks, packed f32x2 Kahan -------
template <int F, int OT, int NC, bool RELU>
__global__ void __launch_bounds__(OT * NC) k_fc(const float* __restrict__ lut,
                                                const float* __restrict__ bias, float* out_ext,
                                                int woff, int O, int aslot, int wslot, int oslot) {
    __shared__ float slut[256];
    __shared__ __align__(16) unsigned short sia[F];
    __shared__ float sred[(NC > 1 ? (NC - 1) * OT * 2 : 1)];
    const int lx = threadIdx.x, cc = threadIdx.y;
    const int tid = lx + OT * cc;
    constexpr int NT = OT * NC;
    const int b = blockIdx.y;
    for (int i = tid; i < 256; i += NT) slut[i] = lut[i];
    for (int f = tid; f < F; f += NT)
        sia[f] = (unsigned short)((unsigned int)g_qa[b * F + f] << 6);
    __syncthreads();

    const int o = blockIdx.x * OT + lx;
    const uchar4* wq = reinterpret_cast<const uchar4*>(g_qw + woff) + o;
    const char* lb = reinterpret_cast<const char*>(slut);
    constexpr int F4C = F / 4 / NC;
    u64 S0 = 0ULL, C0 = 0ULL, S1 = 0ULL, C1 = 0ULL;
#pragma unroll 2
    for (int j = 0; j < F4C; ++j) {
        int f4 = cc * F4C + j;
        uchar4 wv = wq[(size_t)f4 * O];
        ushort4 iv = *reinterpret_cast<const ushort4*>(&sia[f4 * 4]);
        float v0 = *reinterpret_cast<const float*>(lb + (iv.x + (unsigned int)wv.x));
        float v1 = *reinterpret_cast<const float*>(lb + (iv.y + (unsigned int)wv.y));
        float v2 = *reinterpret_cast<const float*>(lb + (iv.z + (unsigned int)wv.z));
        float v3 = *reinterpret_cast<const float*>(lb + (iv.w + (unsigned int)wv.w));
        kahan2(S0, C0, pack2(v0, v1));
        kahan2(S1, C1, pack2(v2, v3));
    }
    float s0, s0h, c0, c0h, s1l, s1h, c1l, c1h;
    unpack2(S0, s0, s0h); unpack2(C0, c0, c0h);
    unpack2(S1, s1l, s1h); unpack2(C1, c1l, c1h);
    kahan(s0, c0, s0h); kahan(s0, c0, -c0h);
    kahan(s0, c0, s1l); kahan(s0, c0, -c1l);
    kahan(s0, c0, s1h); kahan(s0, c0, -c1h);

    if (NC > 1) {
        if (cc > 0) {
            sred[(cc - 1) * OT * 2 + lx * 2 + 0] = s0;
            sred[(cc - 1) * OT * 2 + lx * 2 + 1] = c0;
        }
        __syncthreads();
        if (cc == 0) {
#pragma unroll
            for (int i = 0; i < NC - 1; ++i) {
                kahan(s0, c0, sred[i * OT * 2 + lx * 2 + 0]);
                kahan(s0, c0, -sred[i * OT * 2 + lx * 2 + 1]);
            }
        }
    }

    if (cc == 0) {
        float sc = __fmul_rn(slot_scale(aslot), slot_scale(wslot));
        float v = __fadd_rn(__fmul_rn(s0, sc), bias[o]);
        if (RELU) {
            v = fmaxf(v, 0.0f);
            g_fbuf[(size_t)b * O + o] = v;
            float m = v;
#pragma unroll
            for (int off = 16; off; off >>= 1) m = fmaxf(m, __shfl_xor_sync(0xffffffffu, m, off));
            if ((lx & 31) == 0) atomicMax(&g_maxi[oslot], __float_as_int(m));
        } else {
            out_ext[(size_t)b * O + o] = v;
        }
    }
}

__global__ void __launch_bounds__(320) k_fc_small(const float* __restrict__ lut,
                                                  const float* __restrict__ bias, float* out,
                                                  int woff, int aslot, int wslot) {
    __shared__ float slut[256];
    __shared__ __align__(16) unsigned short sia[4096];
    const int lane = threadIdx.x, o = threadIdx.y, b = blockIdx.x;
    const int tid = lane + 32 * o;
    for (int i = tid; i < 256; i += 320) slut[i] = lut[i];
    for (int f = tid; f < 4096; f += 320)
        sia[f] = (unsigned short)((unsigned int)g_qa[b * 4096 + f] << 6);
    __syncthreads();

    const uchar4* wq = reinterpret_cast<const uchar4*>(g_qw + woff) + o;
    const char* lb = reinterpret_cast<const char*>(slut);
    float s = 0.f, c = 0.f;
#pragma unroll 4
    for (int j = 0; j < 32; ++j) {
        int f4 = j * 32 + lane;
        uchar4 wv = wq[f4 * 10];
        ushort4 iv = *reinterpret_cast<const ushort4*>(&sia[f4 * 4]);
        kahan(s, c, *reinterpret_cast<const float*>(lb + (iv.x + (unsigned int)wv.x)));
        kahan(s, c, *reinterpret_cast<const float*>(lb + (iv.y + (unsigned int)wv.y)));
        kahan(s, c, *reinterpret_cast<const float*>(lb + (iv.z + (unsigned int)wv.z)));
        kahan(s, c, *reinterpret_cast<const float*>(lb + (iv.w + (unsigned int)wv.w)));
    }
#pragma unroll
    for (int off = 16; off; off >>= 1) {
        float ps = __shfl_xor_sync(0xffffffffu, s, off);
        float pc = __shfl_xor_sync(0xffffffffu, c, off);
        kahan(s, c, ps);
        kahan(s, c, -pc);
    }
    if (lane == 0) {
        float sc = __fmul_rn(slot_scale(aslot), slot_scale(wslot));
        out[b * 10 + o] = __fadd_rn(__fmul_rn(s, sc), bias[o]);
    }
}

extern "C" void kernel_launch(void* const* d_in, const int* in_sizes, int n_in,
                              void* d_out, int out_size) {
    const float* x = (const float*)d_in[0];
    const float* w[8]; const float* bb[8];
    for (int i = 0; i < 8; i++) { w[i] = (const float*)d_in[1 + 2 * i]; bb[i] = (const float*)d_in[2 + 2 * i]; }
    const float* luts = (const float*)d_in[17];
    float* out = (float*)d_out;

    k_init<<<1, 16>>>();

    AMaxArgs am;
    int wn[8] = {1728, 110592, 663552, 884736, 589824, 16777216, 16777216, 40960};
    am.b0[0] = 0;
    for (int i = 0; i < 8; i++) {
        am.p[i] = w[i]; am.n[i] = wn[i]; am.slot[i] = i;
        int bl = wn[i] / 8192; if (bl < 1) bl = 1; if (bl > 864) bl = 864;
        am.b0[i + 1] = am.b0[i] + bl;
    }
    am.p[8] = x; am.n[8] = 24576; am.slot[8] = 8;
    am.b0[9] = am.b0[8] + 3;
    k_absmax_all<<<am.b0[9], 256>>>(am);

    QWCArgs qc; for (int i = 0; i < 5; i++) qc.w[i] = w[i];
    k_qw_conv<<<(750144 + 255) / 256, 256>>>(qc);

    // conv pipeline (x-quant fused into conv0)
    k_conv<3, 64, 32, 32, 8, 1, true><<<dim3(1, 4, 256), dim3(64, 1)>>>(
        luts + 0 * 256, bb[0], x, W0OFF, 8, 0, 9);
    k_pool_quant<<<512, 256>>>(64, 32, 32, 9);
    k_conv<64, 192, 16, 16, 8, 4, false><<<dim3(3, 2, 128), dim3(64, 4)>>>(
        luts + 1 * 256, bb[1], nullptr, W1OFF, 9, 1, 10);
    k_pool_quant<<<384, 256>>>(192, 16, 16, 10);
    k_conv<192, 384, 8, 8, 4, 4, false><<<dim3(6, 2, 64), dim3(64, 4)>>>(
        luts + 2 * 256, bb[2], nullptr, W2OFF, 10, 2, 11);
    k_quant_act<<<768, 256>>>(nullptr, 384, 8, 8, 11);
    k_conv<384, 256, 8, 8, 4, 4, false><<<dim3(4, 2, 64), dim3(64, 4)>>>(
        luts + 3 * 256, bb[3], nullptr, W3OFF, 11, 3, 12);
    k_quant_act<<<512, 256>>>(nullptr, 256, 8, 8, 12);
    k_conv<256, 256, 8, 8, 4, 4, false><<<dim3(4, 2, 64), dim3(64, 4)>>>(
        luts + 4 * 256, bb[4], nullptr, W4OFF, 12, 4, 13);
    k_pool_quant_fc<<<128, 256>>>(13);

    // fc weight quant needed only from here on
    QWFArgs qf; qf.w[0] = w[5]; qf.w[1] = w[6]; qf.w[2] = w[7];
    k_qw_fc<<<dim3(32, 128, 3), 256>>>(qf);

    k_fc<4096, 128, 4, true><<<dim3(32, 8), dim3(128, 4)>>>(luts + 5 * 256, bb[5], nullptr, W5OFF, 4096, 13, 5, 14);
    k_quant_act_fc<<<128, 256>>>(14);
    k_fc<4096, 128, 4, true><<<dim3(32, 8), dim3(128, 4)>>>(luts + 6 * 256, bb[6], nullptr, W6OFF, 4096, 14, 6, 15);
    k_quant_act_fc<<<128, 256>>>(15);
    k_fc_small<<<8, dim3(32, 10)>>>(luts + 7 * 256, bb[7], out, W7OFF, 15, 7);
}

// round 13
// speedup vs baseline: 1.1111x; 1.1111x over previous
#include <cuda_runtime.h>

#define BATCH 8
typedef unsigned long long u64;

__device__ __align__(16) unsigned char g_qw[36595968];
__device__ __align__(16) unsigned char g_qa[262144];
__device__ __align__(16) float g_fbuf[524288];
// max bits: 0..7 = |w0..7|, 8 = |x|, 9..13 = conv0..4 out, 14/15 = fc5/6 out
__device__ int g_maxi[16];

#define W0OFF 0
#define W1OFF 2304
#define W2OFF 149760
#define W3OFF 1034496
#define W4OFF 2214144
#define W5OFF 3000576
#define W6OFF 19777792
#define W7OFF 36555008

__device__ __forceinline__ float slot_scale(int s) {
    return fmaxf(__fdiv_rn(__int_as_float(g_maxi[s]), 7.0f), 1e-8f);
}
__device__ __forceinline__ unsigned int quant_idx(float x, float s) {
    float q = rintf(__fdiv_rn(x, s));  // half-even, exact div
    q = fminf(fmaxf(q, -8.0f), 7.0f);
    return (unsigned int)((int)q + 8);
}
__device__ __forceinline__ void kahan(float& s, float& c, float val) {
    float y = __fadd_rn(val, -c);
    float t = __fadd_rn(s, y);
    c = __fadd_rn(__fadd_rn(t, -s), -y);
    s = t;
}
__device__ __forceinline__ u64 pack2(float lo, float hi) {
    u64 v; asm("mov.b64 %0, {%1, %2};" : "=l"(v) : "f"(lo), "f"(hi)); return v;
}
__device__ __forceinline__ void unpack2(u64 v, float& lo, float& hi) {
    asm("mov.b64 {%0, %1}, %2;" : "=f"(lo), "=f"(hi) : "l"(v));
}
__device__ __forceinline__ void kahan2(u64& s, u64& c, u64 val) {
    u64 y, t, d;
    asm("sub.rn.f32x2 %0, %1, %2;" : "=l"(y) : "l"(val), "l"(c));
    asm("add.rn.f32x2 %0, %1, %2;" : "=l"(t) : "l"(s), "l"(y));
    asm("sub.rn.f32x2 %0, %1, %2;" : "=l"(d) : "l"(t), "l"(s));
    asm("sub.rn.f32x2 %0, %1, %2;" : "=l"(c) : "l"(d), "l"(y));
    s = t;
}
#define NEG2(v) ((v) ^ 0x8000000080000000ULL)

__global__ void k_init() { if (threadIdx.x < 16) g_maxi[threadIdx.x] = 0; }

struct AMaxArgs { const float* p[9]; int n[9]; int slot[9]; int b0[10]; };
__global__ void k_absmax_all(AMaxArgs a) {
    int seg = 0;
#pragma unroll
    for (int i = 1; i < 9; i++) if ((int)blockIdx.x >= a.b0[i]) seg = i;
    int lb = blockIdx.x - a.b0[seg], nb = a.b0[seg + 1] - a.b0[seg];
    const float4* p4 = (const float4*)a.p[seg];
    int n4 = a.n[seg] >> 2;
    float m = 0.0f;
    for (int i = lb * 256 + threadIdx.x; i < n4; i += nb * 256) {
        float4 v = p4[i];
        m = fmaxf(m, fmaxf(fmaxf(fabsf(v.x), fabsf(v.y)), fmaxf(fabsf(v.z), fabsf(v.w))));
    }
#pragma unroll
    for (int o = 16; o; o >>= 1) m = fmaxf(m, __shfl_xor_sync(0xffffffffu, m, o));
    if ((threadIdx.x & 31) == 0) atomicMax(&g_maxi[a.slot[seg]], __float_as_int(m));
}

struct QWCArgs { const float* w[5]; };
__global__ void k_qw_conv(QWCArgs a) {
    const int OA[5] = {64, 192, 384, 256, 256}, CA[5] = {3, 64, 192, 384, 256};
    const int WO[5] = {W0OFF, W1OFF, W2OFF, W3OFF, W4OFF};
    const int BASE[6] = {0, 576, 37440, 258624, 553536, 750144};
    int idx = blockIdx.x * blockDim.x + threadIdx.x;
    if (idx >= 750144) return;
    int l = 0;
#pragma unroll
    for (int i = 1; i < 5; i++) if (idx >= BASE[i]) l = i;
    int li = idx - BASE[l], O = OA[l], C = CA[l];
    float s = slot_scale(l);
    int o = li % O, ckh = li / O, c = ckh / 3, kh = ckh % 3;
    const float* src = a.w[l] + ((size_t)(o * C + c) * 3 + kh) * 3;
    uchar4 v;
    v.x = (unsigned char)(quant_idx(src[0], s) << 2);
    v.y = (unsigned char)(quant_idx(src[1], s) << 2);
    v.z = (unsigned char)(quant_idx(src[2], s) << 2);
    v.w = 0;
    reinterpret_cast<uchar4*>(g_qw + WO[l])[(size_t)ckh * O + o] = v;
}

// ---- fused fc weight quant, float4 loads (grid.z = layer) ----
struct QWFArgs { const float* w[3]; };
__global__ void k_qw_fc(QWFArgs a) {
    const int OA[3] = {4096, 4096, 10};
    const int WO[3] = {W5OFF, W6OFF, W7OFF};
    const int z = blockIdx.z, F = 4096, O = OA[z];
    __shared__ unsigned char t[128][33];
    float s = slot_scale(5 + z);
    int f0 = blockIdx.x * 128, o0 = blockIdx.y * 32;
    if (o0 >= O) return;
    const float* w = a.w[z];
    // 32 o-rows x 32 float4 = 128 f-columns; coalesced 128B per warp
    for (int i = threadIdx.x; i < 32 * 32; i += blockDim.x) {
        int ol = i >> 5, f4l = i & 31, o = o0 + ol;
        float4 wv4 = make_float4(0.f, 0.f, 0.f, 0.f);
        if (o < O)
            wv4 = *reinterpret_cast<const float4*>(&w[(size_t)o * F + f0 + f4l * 4]);
        t[f4l * 4 + 0][ol] = (unsigned char)(quant_idx(wv4.x, s) << 2);
        t[f4l * 4 + 1][ol] = (unsigned char)(quant_idx(wv4.y, s) << 2);
        t[f4l * 4 + 2][ol] = (unsigned char)(quant_idx(wv4.z, s) << 2);
        t[f4l * 4 + 3][ol] = (unsigned char)(quant_idx(wv4.w, s) << 2);
    }
    __syncthreads();
    for (int i = threadIdx.x; i < 32 * 32; i += blockDim.x) {
        int f4l = i >> 5, ol = i & 31, o = o0 + ol;
        if (o >= O) continue;
        uchar4 v;
        v.x = t[f4l * 4 + 0][ol]; v.y = t[f4l * 4 + 1][ol];
        v.z = t[f4l * 4 + 2][ol]; v.w = t[f4l * 4 + 3][ol];
        reinterpret_cast<uchar4*>(g_qw + WO[z])[(size_t)(f0 / 4 + f4l) * O + o] = v;
    }
}

__global__ void k_quant_act(const float* in, int C, int H, int W, int slot) {
    const float* src = in ? in : g_fbuf;
    int n = BATCH * C * H * W;
    float s = slot_scale(slot);
    for (int idx = blockIdx.x * blockDim.x + threadIdx.x; idx < n; idx += gridDim.x * blockDim.x) {
        int w = idx % W, t = idx / W, h = t % H; t /= H;
        int c = t % C, b = t / C;
        g_qa[((b * H + h) * C + c) * W + w] = (unsigned char)quant_idx(src[idx], s);
    }
}

__global__ void k_pool_quant(int C, int H, int W, int slot) {
    int H2 = H >> 1, W2 = W >> 1, n = BATCH * C * H2 * W2;
    float s = slot_scale(slot);
    for (int idx = blockIdx.x * blockDim.x + threadIdx.x; idx < n; idx += gridDim.x * blockDim.x) {
        int w = idx % W2, t = idx / W2, h = t % H2; t /= H2;
        int c = t % C, b = t / C;
        const float* p = g_fbuf + (((size_t)(b * C + c) * H + 2 * h) * W + 2 * w);
        float v = fmaxf(fmaxf(p[0], p[1]), fmaxf(p[W], p[W + 1]));
        g_qa[((b * H2 + h) * C + c) * W2 + w] = (unsigned char)quant_idx(v, s);
    }
}

__global__ void k_pool_quant_fc(int slot) {
    int n = BATCH * 4096;
    float s = slot_scale(slot);
    for (int idx = blockIdx.x * blockDim.x + threadIdx.x; idx < n; idx += gridDim.x * blockDim.x) {
        int w = idx % 4, h = (idx / 4) % 4, c = (idx / 16) % 256, b = idx / 4096;
        const float* p = g_fbuf + (((size_t)(b * 256 + c) * 8 + 2 * h) * 8 + 2 * w);
        float v = fmaxf(fmaxf(p[0], p[1]), fmaxf(p[8], p[9]));
        g_qa[b * 4096 + (c * 16 + h * 4 + w)] = (unsigned char)quant_idx(v, s);
    }
}

__global__ void k_quant_act_fc(int slot) {
    float s = slot_scale(slot);
    int idx = blockIdx.x * blockDim.x + threadIdx.x;
    if (idx < BATCH * 4096) g_qa[idx] = (unsigned char)quant_idx(g_fbuf[idx], s);
}

// ------- LUT conv: 64 o-lanes x NC chunks; QUANT fuses x-quant (conv0 only) -------
template <int C, int O, int H, int W, int WT, int NC, bool QUANT>
__global__ void __launch_bounds__(64 * NC) k_conv(const float* __restrict__ lut,
                                                  const float* __restrict__ bias,
                                                  const float* __restrict__ fsrc,
                                                  int woff, int aslot, int wslot, int oslot) {
    constexpr int TW = WT + 4;   // padded row; only WT+2 entries used
    constexpr int WP = WT / 2;   // packed chains
    __shared__ float slut[256];
    __shared__ __align__(16) unsigned short sia[3 * C * TW];
    __shared__ u64 sred[(NC > 1 ? (NC - 1) * 64 * (2 * WP + 1) : 1)];
    const int lane_o = threadIdx.x;  // 0..63
    const int cc = threadIdx.y;      // 0..NC-1
    const int tid = lane_o + 64 * cc;
    constexpr int NT = 64 * NC;
    const int o = blockIdx.x * 64 + lane_o;
    const int w0 = blockIdx.y * WT;
    const int b = blockIdx.z / H, h = blockIdx.z % H;

    for (int i = tid; i < 256; i += NT) slut[i] = lut[i];
    {
        float sa = QUANT ? slot_scale(aslot) : 0.0f;
        for (int i = tid; i < 3 * C * TW; i += NT) {
            int r = i / (C * TW), rem = i - r * C * TW, c = rem / TW, ww = rem - c * TW;
            int gh = h + r - 1, gw = w0 + ww - 1;
            unsigned int v = 8;  // quantized-zero level: padding goes through the LUT
            if (ww < WT + 2 && (unsigned)gh < (unsigned)H && (unsigned)gw < (unsigned)W) {
                if (QUANT)
                    v = quant_idx(fsrc[((size_t)(b * C + c) * H + gh) * W + gw], sa);
                else
                    v = g_qa[((b * H + gh) * C + c) * W + gw];
            }
            sia[i] = (unsigned short)(v << 6);
        }
    }
    __syncthreads();

    u64 acc2[WP], cmp2[WP];
#pragma unroll
    for (int i = 0; i < WP; ++i) { acc2[i] = 0ULL; cmp2[i] = 0ULL; }
    const uchar4* wq = reinterpret_cast<const uchar4*>(g_qw + woff) + o;
    const char* lb = reinterpret_cast<const char*>(slut);
    constexpr int CS = C / NC;
    const int cbeg = cc * CS;

    for (int c = cbeg; c < cbeg + CS; ++c) {
#pragma unroll
        for (int kh = 0; kh < 3; ++kh) {
            uchar4 wv = wq[(c * 3 + kh) * O];
            const unsigned short* row = &sia[(kh * C + c) * TW];
            unsigned int rv[WT + 2];
#pragma unroll
            for (int i = 0; i < WT + 2; ++i) rv[i] = row[i];
            unsigned int woffs[3] = {wv.x, wv.y, wv.z};
#pragma unroll
            for (int kw = 0; kw < 3; ++kw)
#pragma unroll
                for (int wp = 0; wp < WP; ++wp) {
                    float v0 = *reinterpret_cast<const float*>(lb + (rv[2 * wp + kw] + woffs[kw]));
                    float v1 = *reinterpret_cast<const float*>(lb + (rv[2 * wp + 1 + kw] + woffs[kw]));
                    kahan2(acc2[wp], cmp2[wp], pack2(v0, v1));
                }
        }
    }

    if (NC > 1) {
        constexpr int STR = 2 * WP + 1;
        if (cc > 0) {
            u64* dp = &sred[((cc - 1) * 64 + lane_o) * STR];
#pragma unroll
            for (int i = 0; i < WP; ++i) { dp[i] = acc2[i]; dp[WP + i] = cmp2[i]; }
        }
        __syncthreads();
        if (cc == 0) {
#pragma unroll
            for (int i = 0; i < NC - 1; ++i) {
                const u64* sp = &sred[(i * 64 + lane_o) * STR];
#pragma unroll
                for (int wp = 0; wp < WP; ++wp) {
                    kahan2(acc2[wp], cmp2[wp], sp[wp]);
                    kahan2(acc2[wp], cmp2[wp], NEG2(sp[WP + wp]));
                }
            }
        }
    }

    if (cc == 0) {
        float sc = __fmul_rn(slot_scale(aslot), slot_scale(wslot));
        float bv = bias[o], m = 0.0f;
#pragma unroll
        for (int wp = 0; wp < WP; ++wp) {
            float a0, a1;
            unpack2(acc2[wp], a0, a1);
            float v0 = fmaxf(__fadd_rn(__fmul_rn(a0, sc), bv), 0.0f);
            float v1 = fmaxf(__fadd_rn(__fmul_rn(a1, sc), bv), 0.0f);
            size_t base = ((size_t)(b * O + o) * H + h) * W + w0 + 2 * wp;
            g_fbuf[base] = v0;
            g_fbuf[base + 1] = v1;
            m = fmaxf(m, fmaxf(v0, v1));
        }
#pragma unroll
        for (int off = 16; off; off >>= 1) m = fmaxf(m, __shfl_xor_sync(0xffffffffu, m, off));
        if ((lane_o & 31) == 0) atomicMax(&g_maxi[oslot], __float_as_int(m));
    }
}

// ------- LUT fc: OT o-lanes x NC f-chunks, packed f32x2 Kahan -------
template <int F, int OT, int NC, bool RELU>
__global__ void __launch_bounds__(OT * NC) k_fc(const float* __restrict__ lut,
                                                const float* __restrict__ bias, float* out_ext,
                                                int woff, int O, int aslot, int wslot, int oslot) {
    __shared__ float slut[256];
    __shared__ __align__(16) unsigned short sia[F];
    __shared__ float sred[(NC > 1 ? (NC - 1) * OT * 2 : 1)];
    const int lx = threadIdx.x, cc = threadIdx.y;
    const int tid = lx + OT * cc;
    constexpr int NT = OT * NC;
    const int b = blockIdx.y;
    for (int i = tid; i < 256; i += NT) slut[i] = lut[i];
    for (int f = tid; f < F; f += NT)
        sia[f] = (unsigned short)((unsigned int)g_qa[b * F + f] << 6);
    __syncthreads();

    const int o = blockIdx.x * OT + lx;
    const uchar4* wq = reinterpret_cast<const uchar4*>(g_qw + woff) + o;
    const char* lb = reinterpret_cast<const char*>(slut);
    constexpr int F4C = F / 4 / NC;
    u64 S0 = 0ULL, C0 = 0ULL, S1 = 0ULL, C1 = 0ULL;
#pragma unroll 2
    for (int j = 0; j < F4C; ++j) {
        int f4 = cc * F4C + j;
        uchar4 wv = wq[(size_t)f4 * O];
        ushort4 iv = *reinterpret_cast<const ushort4*>(&sia[f4 * 4]);
        float v0 = *reinterpret_cast<const float*>(lb + (iv.x + (unsigned int)wv.x));
        float v1 = *reinterpret_cast<const float*>(lb + (iv.y + (unsigned int)wv.y));
        float v2 = *reinterpret_cast<const float*>(lb + (iv.z + (unsigned int)wv.z));
        float v3 = *reinterpret_cast<const float*>(lb + (iv.w + (unsigned int)wv.w));
        kahan2(S0, C0, pack2(v0, v1));
        kahan2(S1, C1, pack2(v2, v3));
    }
    float s0, s0h, c0, c0h, s1l, s1h, c1l, c1h;
    unpack2(S0, s0, s0h); unpack2(C0, c0, c0h);
    unpack2(S1, s1l, s1h); unpack2(C1, c1l, c1h);
    kahan(s0, c0, s0h); kahan(s0, c0, -c0h);
    kahan(s0, c0, s1l); kahan(s0, c0, -c1l);
    kahan(s0, c0, s1h); kahan(s0, c0, -c1h);

    if (NC > 1) {
        if (cc > 0) {
            sred[(cc - 1) * OT * 2 + lx * 2 + 0] = s0;
            sred[(cc - 1) * OT * 2 + lx * 2 + 1] = c0;
        }
        __syncthreads();
        if (cc == 0) {
#pragma unroll
            for (int i = 0; i < NC - 1; ++i) {
                kahan(s0, c0, sred[i * OT * 2 + lx * 2 + 0]);
                kahan(s0, c0, -sred[i * OT * 2 + lx * 2 + 1]);
            }
        }
    }

    if (cc == 0) {
        float sc = __fmul_rn(slot_scale(aslot), slot_scale(wslot));
        float v = __fadd_rn(__fmul_rn(s0, sc), bias[o]);
        if (RELU) {
            v = fmaxf(v, 0.0f);
            g_fbuf[(size_t)b * O + o] = v;
            float m = v;
#pragma unroll
            for (int off = 16; off; off >>= 1) m = fmaxf(m, __shfl_xor_sync(0xffffffffu, m, off));
            if ((lx & 31) == 0) atomicMax(&g_maxi[oslot], __float_as_int(m));
        } else {
            out_ext[(size_t)b * O + o] = v;
        }
    }
}

__global__ void __launch_bounds__(320) k_fc_small(const float* __restrict__ lut,
                                                  const float* __restrict__ bias, float* out,
                                                  int woff, int aslot, int wslot) {
    __shared__ float slut[256];
    __shared__ __align__(16) unsigned short sia[4096];
    const int lane = threadIdx.x, o = threadIdx.y, b = blockIdx.x;
    const int tid = lane + 32 * o;
    for (int i = tid; i < 256; i += 320) slut[i] = lut[i];
    for (int f = tid; f < 4096; f += 320)
        sia[f] = (unsigned short)((unsigned int)g_qa[b * 4096 + f] << 6);
    __syncthreads();

    const uchar4* wq = reinterpret_cast<const uchar4*>(g_qw + woff) + o;
    const char* lb = reinterpret_cast<const char*>(slut);
    float s = 0.f, c = 0.f;
#pragma unroll 4
    for (int j = 0; j < 32; ++j) {
        int f4 = j * 32 + lane;
        uchar4 wv = wq[f4 * 10];
        ushort4 iv = *reinterpret_cast<const ushort4*>(&sia[f4 * 4]);
        kahan(s, c, *reinterpret_cast<const float*>(lb + (iv.x + (unsigned int)wv.x)));
        kahan(s, c, *reinterpret_cast<const float*>(lb + (iv.y + (unsigned int)wv.y)));
        kahan(s, c, *reinterpret_cast<const float*>(lb + (iv.z + (unsigned int)wv.z)));
        kahan(s, c, *reinterpret_cast<const float*>(lb + (iv.w + (unsigned int)wv.w)));
    }
#pragma unroll
    for (int off = 16; off; off >>= 1) {
        float ps = __shfl_xor_sync(0xffffffffu, s, off);
        float pc = __shfl_xor_sync(0xffffffffu, c, off);
        kahan(s, c, ps);
        kahan(s, c, -pc);
    }
    if (lane == 0) {
        float sc = __fmul_rn(slot_scale(aslot), slot_scale(wslot));
        out[b * 10 + o] = __fadd_rn(__fmul_rn(s, sc), bias[o]);
    }
}

extern "C" void kernel_launch(void* const* d_in, const int* in_sizes, int n_in,
                              void* d_out, int out_size) {
    const float* x = (const float*)d_in[0];
    const float* w[8]; const float* bb[8];
    for (int i = 0; i < 8; i++) { w[i] = (const float*)d_in[1 + 2 * i]; bb[i] = (const float*)d_in[2 + 2 * i]; }
    const float* luts = (const float*)d_in[17];
    float* out = (float*)d_out;

    k_init<<<1, 16>>>();

    AMaxArgs am;
    int wn[8] = {1728, 110592, 663552, 884736, 589824, 16777216, 16777216, 40960};
    am.b0[0] = 0;
    for (int i = 0; i < 8; i++) {
        am.p[i] = w[i]; am.n[i] = wn[i]; am.slot[i] = i;
        int bl = wn[i] / 8192; if (bl < 1) bl = 1; if (bl > 864) bl = 864;
        am.b0[i + 1] = am.b0[i] + bl;
    }
    am.p[8] = x; am.n[8] = 24576; am.slot[8] = 8;
    am.b0[9] = am.b0[8] + 3;
    k_absmax_all<<<am.b0[9], 256>>>(am);

    QWCArgs qc; for (int i = 0; i < 5; i++) qc.w[i] = w[i];
    k_qw_conv<<<(750144 + 255) / 256, 256>>>(qc);

    // conv pipeline: R11-proven configs (WT=8), x-quant fused into conv0
    k_conv<3, 64, 32, 32, 8, 1, true><<<dim3(1, 4, 256), dim3(64, 1)>>>(
        luts + 0 * 256, bb[0], x, W0OFF, 8, 0, 9);
    k_pool_quant<<<512, 256>>>(64, 32, 32, 9);
    k_conv<64, 192, 16, 16, 8, 2, false><<<dim3(3, 2, 128), dim3(64, 2)>>>(
        luts + 1 * 256, bb[1], nullptr, W1OFF, 9, 1, 10);
    k_pool_quant<<<384, 256>>>(192, 16, 16, 10);
    k_conv<192, 384, 8, 8, 8, 4, false><<<dim3(6, 1, 64), dim3(64, 4)>>>(
        luts + 2 * 256, bb[2], nullptr, W2OFF, 10, 2, 11);
    k_quant_act<<<768, 256>>>(nullptr, 384, 8, 8, 11);
    k_conv<384, 256, 8, 8, 8, 6, false><<<dim3(4, 1, 64), dim3(64, 6)>>>(
        luts + 3 * 256, bb[3], nullptr, W3OFF, 11, 3, 12);
    k_quant_act<<<512, 256>>>(nullptr, 256, 8, 8, 12);
    k_conv<256, 256, 8, 8, 8, 4, false><<<dim3(4, 1, 64), dim3(64, 4)>>>(
        luts + 4 * 256, bb[4], nullptr, W4OFF, 12, 4, 13);
    k_pool_quant_fc<<<128, 256>>>(13);

    // fc weight quant needed only from here on (overlaps nothing but orders profile nicely)
    QWFArgs qf; qf.w[0] = w[5]; qf.w[1] = w[6]; qf.w[2] = w[7];
    k_qw_fc<<<dim3(32, 128, 3), 256>>>(qf);

    k_fc<4096, 128, 4, true><<<dim3(32, 8), dim3(128, 4)>>>(luts + 5 * 256, bb[5], nullptr, W5OFF, 4096, 13, 5, 14);
    k_quant_act_fc<<<128, 256>>>(14);
    k_fc<4096, 128, 4, true><<<dim3(32, 8), dim3(128, 4)>>>(luts + 6 * 256, bb[6], nullptr, W6OFF, 4096, 14, 6, 15);
    k_quant_act_fc<<<128, 256>>>(15);
    k_fc_small<<<8, dim3(32, 10)>>>(luts + 7 * 256, bb[7], out, W7OFF, 15, 7);
}

// round 14
// speedup vs baseline: 1.1498x; 1.0348x over previous
#include <cuda_runtime.h>

#define BATCH 8
typedef unsigned long long u64;

__device__ __align__(16) unsigned char g_qw[36595968];
__device__ __align__(16) unsigned char g_qa[262144];
__device__ __align__(16) float g_fbuf[524288];
// max bits: 0..7 = |w0..7|, 8 = |x|, 9..13 = conv0..4 out, 14/15 = fc5/6 out
__device__ int g_maxi[16];

#define W0OFF 0
#define W1OFF 2304
#define W2OFF 149760
#define W3OFF 1034496
#define W4OFF 2214144
#define W5OFF 3000576
#define W6OFF 19777792
#define W7OFF 36555008

__device__ __forceinline__ float slot_scale(int s) {
    return fmaxf(__fdiv_rn(__int_as_float(g_maxi[s]), 7.0f), 1e-8f);
}
__device__ __forceinline__ unsigned int quant_idx(float x, float s) {
    float q = rintf(__fdiv_rn(x, s));  // half-even, exact div
    q = fminf(fmaxf(q, -8.0f), 7.0f);
    return (unsigned int)((int)q + 8);
}
__device__ __forceinline__ void kahan(float& s, float& c, float val) {
    float y = __fadd_rn(val, -c);
    float t = __fadd_rn(s, y);
    c = __fadd_rn(__fadd_rn(t, -s), -y);
    s = t;
}
__device__ __forceinline__ u64 pack2(float lo, float hi) {
    u64 v; asm("mov.b64 %0, {%1, %2};" : "=l"(v) : "f"(lo), "f"(hi)); return v;
}
__device__ __forceinline__ void unpack2(u64 v, float& lo, float& hi) {
    asm("mov.b64 {%0, %1}, %2;" : "=f"(lo), "=f"(hi) : "l"(v));
}
__device__ __forceinline__ void kahan2(u64& s, u64& c, u64 val) {
    u64 y, t, d;
    asm("sub.rn.f32x2 %0, %1, %2;" : "=l"(y) : "l"(val), "l"(c));
    asm("add.rn.f32x2 %0, %1, %2;" : "=l"(t) : "l"(s), "l"(y));
    asm("sub.rn.f32x2 %0, %1, %2;" : "=l"(d) : "l"(t), "l"(s));
    asm("sub.rn.f32x2 %0, %1, %2;" : "=l"(c) : "l"(d), "l"(y));
    s = t;
}
#define NEG2(v) ((v) ^ 0x8000000080000000ULL)

__global__ void k_init() { if (threadIdx.x < 16) g_maxi[threadIdx.x] = 0; }

struct AMaxArgs { const float* p[9]; int n[9]; int slot[9]; int b0[10]; };
__global__ void k_absmax_all(AMaxArgs a) {
    int seg = 0;
#pragma unroll
    for (int i = 1; i < 9; i++) if ((int)blockIdx.x >= a.b0[i]) seg = i;
    int lb = blockIdx.x - a.b0[seg], nb = a.b0[seg + 1] - a.b0[seg];
    const float4* p4 = (const float4*)a.p[seg];
    int n4 = a.n[seg] >> 2;
    float m = 0.0f;
    for (int i = lb * 256 + threadIdx.x; i < n4; i += nb * 256) {
        float4 v = p4[i];
        m = fmaxf(m, fmaxf(fmaxf(fabsf(v.x), fabsf(v.y)), fmaxf(fabsf(v.z), fabsf(v.w))));
    }
#pragma unroll
    for (int o = 16; o; o >>= 1) m = fmaxf(m, __shfl_xor_sync(0xffffffffu, m, o));
    if ((threadIdx.x & 31) == 0) atomicMax(&g_maxi[a.slot[seg]], __float_as_int(m));
}

struct QWCArgs { const float* w[5]; };
__global__ void k_qw_conv(QWCArgs a) {
    const int OA[5] = {64, 192, 384, 256, 256}, CA[5] = {3, 64, 192, 384, 256};
    const int WO[5] = {W0OFF, W1OFF, W2OFF, W3OFF, W4OFF};
    const int BASE[6] = {0, 576, 37440, 258624, 553536, 750144};
    int idx = blockIdx.x * blockDim.x + threadIdx.x;
    if (idx >= 750144) return;
    int l = 0;
#pragma unroll
    for (int i = 1; i < 5; i++) if (idx >= BASE[i]) l = i;
    int li = idx - BASE[l], O = OA[l], C = CA[l];
    float s = slot_scale(l);
    int o = li % O, ckh = li / O, c = ckh / 3, kh = ckh % 3;
    const float* src = a.w[l] + ((size_t)(o * C + c) * 3 + kh) * 3;
    uchar4 v;
    v.x = (unsigned char)(quant_idx(src[0], s) << 2);
    v.y = (unsigned char)(quant_idx(src[1], s) << 2);
    v.z = (unsigned char)(quant_idx(src[2], s) << 2);
    v.w = 0;
    reinterpret_cast<uchar4*>(g_qw + WO[l])[(size_t)ckh * O + o] = v;
}

struct QWFArgs { const float* w[3]; };
__global__ void k_qw_fc(QWFArgs a) {
    const int OA[3] = {4096, 4096, 10};
    const int WO[3] = {W5OFF, W6OFF, W7OFF};
    const int z = blockIdx.z, F = 4096, O = OA[z];
    __shared__ unsigned char t[128][33];
    float s = slot_scale(5 + z);
    int f0 = blockIdx.x * 128, o0 = blockIdx.y * 32;
    if (o0 >= O) return;
    const float* w = a.w[z];
    for (int i = threadIdx.x; i < 32 * 32; i += blockDim.x) {
        int ol = i >> 5, f4l = i & 31, o = o0 + ol;
        float4 wv4 = make_float4(0.f, 0.f, 0.f, 0.f);
        if (o < O)
            wv4 = *reinterpret_cast<const float4*>(&w[(size_t)o * F + f0 + f4l * 4]);
        t[f4l * 4 + 0][ol] = (unsigned char)(quant_idx(wv4.x, s) << 2);
        t[f4l * 4 + 1][ol] = (unsigned char)(quant_idx(wv4.y, s) << 2);
        t[f4l * 4 + 2][ol] = (unsigned char)(quant_idx(wv4.z, s) << 2);
        t[f4l * 4 + 3][ol] = (unsigned char)(quant_idx(wv4.w, s) << 2);
    }
    __syncthreads();
    for (int i = threadIdx.x; i < 32 * 32; i += blockDim.x) {
        int f4l = i >> 5, ol = i & 31, o = o0 + ol;
        if (o >= O) continue;
        uchar4 v;
        v.x = t[f4l * 4 + 0][ol]; v.y = t[f4l * 4 + 1][ol];
        v.z = t[f4l * 4 + 2][ol]; v.w = t[f4l * 4 + 3][ol];
        reinterpret_cast<uchar4*>(g_qw + WO[z])[(size_t)(f0 / 4 + f4l) * O + o] = v;
    }
}

__global__ void k_quant_act(const float* in, int C, int H, int W, int slot) {
    const float* src = in ? in : g_fbuf;
    int n = BATCH * C * H * W;
    float s = slot_scale(slot);
    for (int idx = blockIdx.x * blockDim.x + threadIdx.x; idx < n; idx += gridDim.x * blockDim.x) {
        int w = idx % W, t = idx / W, h = t % H; t /= H;
        int c = t % C, b = t / C;
        g_qa[((b * H + h) * C + c) * W + w] = (unsigned char)quant_idx(src[idx], s);
    }
}

__global__ void k_pool_quant(int C, int H, int W, int slot) {
    int H2 = H >> 1, W2 = W >> 1, n = BATCH * C * H2 * W2;
    float s = slot_scale(slot);
    for (int idx = blockIdx.x * blockDim.x + threadIdx.x; idx < n; idx += gridDim.x * blockDim.x) {
        int w = idx % W2, t = idx / W2, h = t % H2; t /= H2;
        int c = t % C, b = t / C;
        const float* p = g_fbuf + (((size_t)(b * C + c) * H + 2 * h) * W + 2 * w);
        float v = fmaxf(fmaxf(p[0], p[1]), fmaxf(p[W], p[W + 1]));
        g_qa[((b * H2 + h) * C + c) * W2 + w] = (unsigned char)quant_idx(v, s);
    }
}

__global__ void k_pool_quant_fc(int slot) {
    int n = BATCH * 4096;
    float s = slot_scale(slot);
    for (int idx = blockIdx.x * blockDim.x + threadIdx.x; idx < n; idx += gridDim.x * blockDim.x) {
        int w = idx % 4, h = (idx / 4) % 4, c = (idx / 16) % 256, b = idx / 4096;
        const float* p = g_fbuf + (((size_t)(b * 256 + c) * 8 + 2 * h) * 8 + 2 * w);
        float v = fmaxf(fmaxf(p[0], p[1]), fmaxf(p[8], p[9]));
        g_qa[b * 4096 + (c * 16 + h * 4 + w)] = (unsigned char)quant_idx(v, s);
    }
}

__global__ void k_quant_act_fc(int slot) {
    float s = slot_scale(slot);
    int idx = blockIdx.x * blockDim.x + threadIdx.x;
    if (idx < BATCH * 4096) g_qa[idx] = (unsigned char)quant_idx(g_fbuf[idx], s);
}

// ------- LUT conv: 64 o-lanes x NC chunks; 12 Kahan chains (wp x kw) -------
template <int C, int O, int H, int W, int WT, int NC, bool QUANT>
__global__ void __launch_bounds__(64 * NC) k_conv(const float* __restrict__ lut,
                                                  const float* __restrict__ bias,
                                                  const float* __restrict__ fsrc,
                                                  int woff, int aslot, int wslot, int oslot) {
    constexpr int TW = WT + 4;   // 12 u16 = 24B rows, 8B-aligned
    constexpr int WP = WT / 2;   // 4 packed output pairs
    __shared__ float slut[256];
    __shared__ __align__(16) unsigned short sia[3 * C * TW];
    __shared__ u64 sred[(NC > 1 ? (NC - 1) * 64 * (2 * WP + 1) : 1)];
    const int lane_o = threadIdx.x;
    const int cc = threadIdx.y;
    const int tid = lane_o + 64 * cc;
    constexpr int NT = 64 * NC;
    const int o = blockIdx.x * 64 + lane_o;
    const int w0 = blockIdx.y * WT;
    const int b = blockIdx.z / H, h = blockIdx.z % H;

    for (int i = tid; i < 256; i += NT) slut[i] = lut[i];
    {
        float sa = QUANT ? slot_scale(aslot) : 0.0f;
        for (int i = tid; i < 3 * C * TW; i += NT) {
            int r = i / (C * TW), rem = i - r * C * TW, c = rem / TW, ww = rem - c * TW;
            int gh = h + r - 1, gw = w0 + ww - 1;
            unsigned int v = 8;  // quantized-zero level: padding goes through the LUT
            if (ww < WT + 2 && (unsigned)gh < (unsigned)H && (unsigned)gw < (unsigned)W) {
                if (QUANT)
                    v = quant_idx(fsrc[((size_t)(b * C + c) * H + gh) * W + gw], sa);
                else
                    v = g_qa[((b * H + gh) * C + c) * W + gw];
            }
            sia[i] = (unsigned short)(v << 6);
        }
    }
    __syncthreads();

    // 12 independent chains: index kw*WP + wp
    u64 acc2[3 * WP], cmp2[3 * WP];
#pragma unroll
    for (int i = 0; i < 3 * WP; ++i) { acc2[i] = 0ULL; cmp2[i] = 0ULL; }
    const uchar4* wq = reinterpret_cast<const uchar4*>(g_qw + woff) + o;
    const char* lb = reinterpret_cast<const char*>(slut);
    constexpr int CS = C / NC;
    const int cbeg = cc * CS;

    for (int c = cbeg; c < cbeg + CS; ++c) {
#pragma unroll
        for (int kh = 0; kh < 3; ++kh) {
            uchar4 wv = wq[(c * 3 + kh) * O];
            const ushort4* row4 = reinterpret_cast<const ushort4*>(&sia[(kh * C + c) * TW]);
            ushort4 q0 = row4[0], q1 = row4[1], q2 = row4[2];
            unsigned int rv[12] = {q0.x, q0.y, q0.z, q0.w, q1.x, q1.y,
                                   q1.z, q1.w, q2.x, q2.y, q2.z, q2.w};
            unsigned int woffs[3] = {wv.x, wv.y, wv.z};
#pragma unroll
            for (int kw = 0; kw < 3; ++kw)
#pragma unroll
                for (int wp = 0; wp < WP; ++wp) {
                    float v0 = *reinterpret_cast<const float*>(lb + (rv[2 * wp + kw] + woffs[kw]));
                    float v1 = *reinterpret_cast<const float*>(lb + (rv[2 * wp + 1 + kw] + woffs[kw]));
                    kahan2(acc2[kw * WP + wp], cmp2[kw * WP + wp], pack2(v0, v1));
                }
        }
    }
    // fold kw=1,2 chains into kw=0 chains (exact Kahan merge)
#pragma unroll
    for (int wp = 0; wp < WP; ++wp) {
#pragma unroll
        for (int kw = 1; kw < 3; ++kw) {
            kahan2(acc2[wp], cmp2[wp], acc2[kw * WP + wp]);
            kahan2(acc2[wp], cmp2[wp], NEG2(cmp2[kw * WP + wp]));
        }
    }

    if (NC > 1) {
        constexpr int STR = 2 * WP + 1;
        if (cc > 0) {
            u64* dp = &sred[((cc - 1) * 64 + lane_o) * STR];
#pragma unroll
            for (int i = 0; i < WP; ++i) { dp[i] = acc2[i]; dp[WP + i] = cmp2[i]; }
        }
        __syncthreads();
        if (cc == 0) {
#pragma unroll
            for (int i = 0; i < NC - 1; ++i) {
                const u64* sp = &sred[(i * 64 + lane_o) * STR];
#pragma unroll
                for (int wp = 0; wp < WP; ++wp) {
                    kahan2(acc2[wp], cmp2[wp], sp[wp]);
                    kahan2(acc2[wp], cmp2[wp], NEG2(sp[WP + wp]));
                }
            }
        }
    }

    if (cc == 0) {
        float sc = __fmul_rn(slot_scale(aslot), slot_scale(wslot));
        float bv = bias[o], m = 0.0f;
#pragma unroll
        for (int wp = 0; wp < WP; ++wp) {
            float a0, a1;
            unpack2(acc2[wp], a0, a1);
            float v0 = fmaxf(__fadd_rn(__fmul_rn(a0, sc), bv), 0.0f);
            float v1 = fmaxf(__fadd_rn(__fmul_rn(a1, sc), bv), 0.0f);
            size_t base = ((size_t)(b * O + o) * H + h) * W + w0 + 2 * wp;
            g_fbuf[base] = v0;
            g_fbuf[base + 1] = v1;
            m = fmaxf(m, fmaxf(v0, v1));
        }
#pragma unroll
        for (int off = 16; off; off >>= 1) m = fmaxf(m, __shfl_xor_sync(0xffffffffu, m, off));
        if ((lane_o & 31) == 0) atomicMax(&g_maxi[oslot], __float_as_int(m));
    }
}

// ------- LUT fc: OT o-lanes x NC f-chunks, 4 packed Kahan chains -------
template <int F, int OT, int NC, bool RELU>
__global__ void __launch_bounds__(OT * NC) k_fc(const float* __restrict__ lut,
                                                const float* __restrict__ bias, float* out_ext,
                                                int woff, int O, int aslot, int wslot, int oslot) {
    __shared__ float slut[256];
    __shared__ __align__(16) unsigned short sia[F];
    __shared__ float sred[(NC > 1 ? (NC - 1) * OT * 2 : 1)];
    const int lx = threadIdx.x, cc = threadIdx.y;
    const int tid = lx + OT * cc;
    constexpr int NT = OT * NC;
    const int b = blockIdx.y;
    for (int i = tid; i < 256; i += NT) slut[i] = lut[i];
    for (int f = tid; f < F; f += NT)
        sia[f] = (unsigned short)((unsigned int)g_qa[b * F + f] << 6);
    __syncthreads();

    const int o = blockIdx.x * OT + lx;
    const uchar4* wq = reinterpret_cast<const uchar4*>(g_qw + woff) + o;
    const char* lb = reinterpret_cast<const char*>(slut);
    constexpr int F4C = F / 4 / NC;
    u64 S[4] = {0ULL, 0ULL, 0ULL, 0ULL}, Cc[4] = {0ULL, 0ULL, 0ULL, 0ULL};
#pragma unroll 2
    for (int j = 0; j < F4C / 2; ++j) {
#pragma unroll
        for (int k = 0; k < 2; ++k) {
            int f4 = cc * F4C + j * 2 + k;
            uchar4 wv = wq[(size_t)f4 * O];
            ushort4 iv = *reinterpret_cast<const ushort4*>(&sia[f4 * 4]);
            float v0 = *reinterpret_cast<const float*>(lb + (iv.x + (unsigned int)wv.x));
            float v1 = *reinterpret_cast<const float*>(lb + (iv.y + (unsigned int)wv.y));
            float v2 = *reinterpret_cast<const float*>(lb + (iv.z + (unsigned int)wv.z));
            float v3 = *reinterpret_cast<const float*>(lb + (iv.w + (unsigned int)wv.w));
            kahan2(S[k * 2 + 0], Cc[k * 2 + 0], pack2(v0, v1));
            kahan2(S[k * 2 + 1], Cc[k * 2 + 1], pack2(v2, v3));
        }
    }
    // fold chains 1..3 into chain 0 (packed), then to scalar
#pragma unroll
    for (int k = 1; k < 4; ++k) {
        kahan2(S[0], Cc[0], S[k]);
        kahan2(S[0], Cc[0], NEG2(Cc[k]));
    }
    float s0, s0h, c0, c0h;
    unpack2(S[0], s0, s0h); unpack2(Cc[0], c0, c0h);
    kahan(s0, c0, s0h); kahan(s0, c0, -c0h);

    if (NC > 1) {
        if (cc > 0) {
            sred[(cc - 1) * OT * 2 + lx * 2 + 0] = s0;
            sred[(cc - 1) * OT * 2 + lx * 2 + 1] = c0;
        }
        __syncthreads();
        if (cc == 0) {
#pragma unroll
            for (int i = 0; i < NC - 1; ++i) {
                kahan(s0, c0, sred[i * OT * 2 + lx * 2 + 0]);
                kahan(s0, c0, -sred[i * OT * 2 + lx * 2 + 1]);
            }
        }
    }

    if (cc == 0) {
        float sc = __fmul_rn(slot_scale(aslot), slot_scale(wslot));
        float v = __fadd_rn(__fmul_rn(s0, sc), bias[o]);
        if (RELU) {
            v = fmaxf(v, 0.0f);
            g_fbuf[(size_t)b * O + o] = v;
            float m = v;
#pragma unroll
            for (int off = 16; off; off >>= 1) m = fmaxf(m, __shfl_xor_sync(0xffffffffu, m, off));
            if ((lx & 31) == 0) atomicMax(&g_maxi[oslot], __float_as_int(m));
        } else {
            out_ext[(size_t)b * O + o] = v;
        }
    }
}

__global__ void __launch_bounds__(320) k_fc_small(const float* __restrict__ lut,
                                                  const float* __restrict__ bias, float* out,
                                                  int woff, int aslot, int wslot) {
    __shared__ float slut[256];
    __shared__ __align__(16) unsigned short sia[4096];
    const int lane = threadIdx.x, o = threadIdx.y, b = blockIdx.x;
    const int tid = lane + 32 * o;
    for (int i = tid; i < 256; i += 320) slut[i] = lut[i];
    for (int f = tid; f < 4096; f += 320)
        sia[f] = (unsigned short)((unsigned int)g_qa[b * 4096 + f] << 6);
    __syncthreads();

    const uchar4* wq = reinterpret_cast<const uchar4*>(g_qw + woff) + o;
    const char* lb = reinterpret_cast<const char*>(slut);
    float s = 0.f, c = 0.f;
#pragma unroll 4
    for (int j = 0; j < 32; ++j) {
        int f4 = j * 32 + lane;
        uchar4 wv = wq[f4 * 10];
        ushort4 iv = *reinterpret_cast<const ushort4*>(&sia[f4 * 4]);
        kahan(s, c, *reinterpret_cast<const float*>(lb + (iv.x + (unsigned int)wv.x)));
        kahan(s, c, *reinterpret_cast<const float*>(lb + (iv.y + (unsigned int)wv.y)));
        kahan(s, c, *reinterpret_cast<const float*>(lb + (iv.z + (unsigned int)wv.z)));
        kahan(s, c, *reinterpret_cast<const float*>(lb + (iv.w + (unsigned int)wv.w)));
    }
#pragma unroll
    for (int off = 16; off; off >>= 1) {
        float ps = __shfl_xor_sync(0xffffffffu, s, off);
        float pc = __shfl_xor_sync(0xffffffffu, c, off);
        kahan(s, c, ps);
        kahan(s, c, -pc);
    }
    if (lane == 0) {
        float sc = __fmul_rn(slot_scale(aslot), slot_scale(wslot));
        out[b * 10 + o] = __fadd_rn(__fmul_rn(s, sc), bias[o]);
    }
}

extern "C" void kernel_launch(void* const* d_in, const int* in_sizes, int n_in,
                              void* d_out, int out_size) {
    const float* x = (const float*)d_in[0];
    const float* w[8]; const float* bb[8];
    for (int i = 0; i < 8; i++) { w[i] = (const float*)d_in[1 + 2 * i]; bb[i] = (const float*)d_in[2 + 2 * i]; }
    const float* luts = (const float*)d_in[17];
    float* out = (float*)d_out;

    k_init<<<1, 16>>>();

    AMaxArgs am;
    int wn[8] = {1728, 110592, 663552, 884736, 589824, 16777216, 16777216, 40960};
    am.b0[0] = 0;
    for (int i = 0; i < 8; i++) {
        am.p[i] = w[i]; am.n[i] = wn[i]; am.slot[i] = i;
        int bl = wn[i] / 8192; if (bl < 1) bl = 1; if (bl > 864) bl = 864;
        am.b0[i + 1] = am.b0[i] + bl;
    }
    am.p[8] = x; am.n[8] = 24576; am.slot[8] = 8;
    am.b0[9] = am.b0[8] + 3;
    k_absmax_all<<<am.b0[9], 256>>>(am);

    QWCArgs qc; for (int i = 0; i < 5; i++) qc.w[i] = w[i];
    k_qw_conv<<<(750144 + 255) / 256, 256>>>(qc);

    k_conv<3, 64, 32, 32, 8, 1, true><<<dim3(1, 4, 256), dim3(64, 1)>>>(
        luts + 0 * 256, bb[0], x, W0OFF, 8, 0, 9);
    k_pool_quant<<<512, 256>>>(64, 32, 32, 9);
    k_conv<64, 192, 16, 16, 8, 2, false><<<dim3(3, 2, 128), dim3(64, 2)>>>(
        luts + 1 * 256, bb[1], nullptr, W1OFF, 9, 1, 10);
    k_pool_quant<<<384, 256>>>(192, 16, 16, 10);
    k_conv<192, 384, 8, 8, 8, 4, false><<<dim3(6, 1, 64), dim3(64, 4)>>>(
        luts + 2 * 256, bb[2], nullptr, W2OFF, 10, 2, 11);
    k_quant_act<<<768, 256>>>(nullptr, 384, 8, 8, 11);
    k_conv<384, 256, 8, 8, 8, 6, false><<<dim3(4, 1, 64), dim3(64, 6)>>>(
        luts + 3 * 256, bb[3], nullptr, W3OFF, 11, 3, 12);
    k_quant_act<<<512, 256>>>(nullptr, 256, 8, 8, 12);
    k_conv<256, 256, 8, 8, 8, 4, false><<<dim3(4, 1, 64), dim3(64, 4)>>>(
        luts + 4 * 256, bb[4], nullptr, W4OFF, 12, 4, 13);
    k_pool_quant_fc<<<128, 256>>>(13);

    QWFArgs qf; qf.w[0] = w[5]; qf.w[1] = w[6]; qf.w[2] = w[7];
    k_qw_fc<<<dim3(32, 128, 3), 256>>>(qf);

    k_fc<4096, 128, 4, true><<<dim3(32, 8), dim3(128, 4)>>>(luts + 5 * 256, bb[5], nullptr, W5OFF, 4096, 13, 5, 14);
    k_quant_act_fc<<<128, 256>>>(14);
    k_fc<4096, 128, 4, true><<<dim3(32, 8), dim3(128, 4)>>>(luts + 6 * 256, bb[6], nullptr, W6OFF, 4096, 14, 6, 15);
    k_quant_act_fc<<<128, 256>>>(15);
    k_fc_small<<<8, dim3(32, 10)>>>(luts + 7 * 256, bb[7], out, W7OFF, 15, 7);
}

// round 15
// speedup vs baseline: 1.1585x; 1.0076x over previous
#include <cuda_runtime.h>

#define BATCH 8
typedef unsigned long long u64;

__device__ __align__(16) unsigned char g_qw[36595968];
__device__ __align__(16) unsigned char g_qa[262144];
__device__ __align__(16) float g_fbuf[524288];
// max bits: 0..7 = |w0..7|, 8 = |x|, 9..13 = conv0..4 out, 14/15 = fc5/6 out
__device__ int g_maxi[16];

#define W0OFF 0
#define W1OFF 2304
#define W2OFF 149760
#define W3OFF 1034496
#define W4OFF 2214144
#define W5OFF 3000576
#define W6OFF 19777792
#define W7OFF 36555008

__device__ __forceinline__ float slot_scale(int s) {
    return fmaxf(__fdiv_rn(__int_as_float(g_maxi[s]), 7.0f), 1e-8f);
}
__device__ __forceinline__ unsigned int quant_idx(float x, float s) {
    float q = rintf(__fdiv_rn(x, s));  // half-even, exact div
    q = fminf(fmaxf(q, -8.0f), 7.0f);
    return (unsigned int)((int)q + 8);
}
__device__ __forceinline__ void kahan(float& s, float& c, float val) {
    float y = __fadd_rn(val, -c);
    float t = __fadd_rn(s, y);
    c = __fadd_rn(__fadd_rn(t, -s), -y);
    s = t;
}
__device__ __forceinline__ u64 pack2(float lo, float hi) {
    u64 v; asm("mov.b64 %0, {%1, %2};" : "=l"(v) : "f"(lo), "f"(hi)); return v;
}
__device__ __forceinline__ void unpack2(u64 v, float& lo, float& hi) {
    asm("mov.b64 {%0, %1}, %2;" : "=f"(lo), "=f"(hi) : "l"(v));
}
__device__ __forceinline__ void kahan2(u64& s, u64& c, u64 val) {
    u64 y, t, d;
    asm("sub.rn.f32x2 %0, %1, %2;" : "=l"(y) : "l"(val), "l"(c));
    asm("add.rn.f32x2 %0, %1, %2;" : "=l"(t) : "l"(s), "l"(y));
    asm("sub.rn.f32x2 %0, %1, %2;" : "=l"(d) : "l"(t), "l"(s));
    asm("sub.rn.f32x2 %0, %1, %2;" : "=l"(c) : "l"(d), "l"(y));
    s = t;
}
#define NEG2(v) ((v) ^ 0x8000000080000000ULL)

__global__ void k_init() { if (threadIdx.x < 16) g_maxi[threadIdx.x] = 0; }

struct AMaxArgs { const float* p[9]; int n[9]; int slot[9]; int b0[10]; };
__global__ void k_absmax_all(AMaxArgs a) {
    int seg = 0;
#pragma unroll
    for (int i = 1; i < 9; i++) if ((int)blockIdx.x >= a.b0[i]) seg = i;
    int lb = blockIdx.x - a.b0[seg], nb = a.b0[seg + 1] - a.b0[seg];
    const float4* p4 = (const float4*)a.p[seg];
    int n4 = a.n[seg] >> 2;
    float m = 0.0f;
    for (int i = lb * 256 + threadIdx.x; i < n4; i += nb * 256) {
        float4 v = p4[i];
        m = fmaxf(m, fmaxf(fmaxf(fabsf(v.x), fabsf(v.y)), fmaxf(fabsf(v.z), fabsf(v.w))));
    }
#pragma unroll
    for (int o = 16; o; o >>= 1) m = fmaxf(m, __shfl_xor_sync(0xffffffffu, m, o));
    if ((threadIdx.x & 31) == 0) atomicMax(&g_maxi[a.slot[seg]], __float_as_int(m));
}

struct QWCArgs { const float* w[5]; };
__global__ void k_qw_conv(QWCArgs a) {
    const int OA[5] = {64, 192, 384, 256, 256}, CA[5] = {3, 64, 192, 384, 256};
    const int WO[5] = {W0OFF, W1OFF, W2OFF, W3OFF, W4OFF};
    const int BASE[6] = {0, 576, 37440, 258624, 553536, 750144};
    int idx = blockIdx.x * blockDim.x + threadIdx.x;
    if (idx >= 750144) return;
    int l = 0;
#pragma unroll
    for (int i = 1; i < 5; i++) if (idx >= BASE[i]) l = i;
    int li = idx - BASE[l], O = OA[l], C = CA[l];
    float s = slot_scale(l);
    int o = li % O, ckh = li / O, c = ckh / 3, kh = ckh % 3;
    const float* src = a.w[l] + ((size_t)(o * C + c) * 3 + kh) * 3;
    uchar4 v;
    v.x = (unsigned char)(quant_idx(src[0], s) << 2);
    v.y = (unsigned char)(quant_idx(src[1], s) << 2);
    v.z = (unsigned char)(quant_idx(src[2], s) << 2);
    v.w = 0;
    reinterpret_cast<uchar4*>(g_qw + WO[l])[(size_t)ckh * O + o] = v;
}

struct QWFArgs { const float* w[3]; };
__global__ void k_qw_fc(QWFArgs a) {
    const int OA[3] = {4096, 4096, 10};
    const int WO[3] = {W5OFF, W6OFF, W7OFF};
    const int z = blockIdx.z, F = 4096, O = OA[z];
    __shared__ unsigned char t[128][33];
    float s = slot_scale(5 + z);
    int f0 = blockIdx.x * 128, o0 = blockIdx.y * 32;
    if (o0 >= O) return;
    const float* w = a.w[z];
    for (int i = threadIdx.x; i < 32 * 32; i += blockDim.x) {
        int ol = i >> 5, f4l = i & 31, o = o0 + ol;
        float4 wv4 = make_float4(0.f, 0.f, 0.f, 0.f);
        if (o < O)
            wv4 = *reinterpret_cast<const float4*>(&w[(size_t)o * F + f0 + f4l * 4]);
        t[f4l * 4 + 0][ol] = (unsigned char)(quant_idx(wv4.x, s) << 2);
        t[f4l * 4 + 1][ol] = (unsigned char)(quant_idx(wv4.y, s) << 2);
        t[f4l * 4 + 2][ol] = (unsigned char)(quant_idx(wv4.z, s) << 2);
        t[f4l * 4 + 3][ol] = (unsigned char)(quant_idx(wv4.w, s) << 2);
    }
    __syncthreads();
    for (int i = threadIdx.x; i < 32 * 32; i += blockDim.x) {
        int f4l = i >> 5, ol = i & 31, o = o0 + ol;
        if (o >= O) continue;
        uchar4 v;
        v.x = t[f4l * 4 + 0][ol]; v.y = t[f4l * 4 + 1][ol];
        v.z = t[f4l * 4 + 2][ol]; v.w = t[f4l * 4 + 3][ol];
        reinterpret_cast<uchar4*>(g_qw + WO[z])[(size_t)(f0 / 4 + f4l) * O + o] = v;
    }
}

__global__ void k_quant_act(const float* in, int C, int H, int W, int slot) {
    const float* src = in ? in : g_fbuf;
    int n = BATCH * C * H * W;
    float s = slot_scale(slot);
    for (int idx = blockIdx.x * blockDim.x + threadIdx.x; idx < n; idx += gridDim.x * blockDim.x) {
        int w = idx % W, t = idx / W, h = t % H; t /= H;
        int c = t % C, b = t / C;
        g_qa[((b * H + h) * C + c) * W + w] = (unsigned char)quant_idx(src[idx], s);
    }
}

__global__ void k_pool_quant(int C, int H, int W, int slot) {
    int H2 = H >> 1, W2 = W >> 1, n = BATCH * C * H2 * W2;
    float s = slot_scale(slot);
    for (int idx = blockIdx.x * blockDim.x + threadIdx.x; idx < n; idx += gridDim.x * blockDim.x) {
        int w = idx % W2, t = idx / W2, h = t % H2; t /= H2;
        int c = t % C, b = t / C;
        const float* p = g_fbuf + (((size_t)(b * C + c) * H + 2 * h) * W + 2 * w);
        float v = fmaxf(fmaxf(p[0], p[1]), fmaxf(p[W], p[W + 1]));
        g_qa[((b * H2 + h) * C + c) * W2 + w] = (unsigned char)quant_idx(v, s);
    }
}

__global__ void k_pool_quant_fc(int slot) {
    int n = BATCH * 4096;
    float s = slot_scale(slot);
    for (int idx = blockIdx.x * blockDim.x + threadIdx.x; idx < n; idx += gridDim.x * blockDim.x) {
        int w = idx % 4, h = (idx / 4) % 4, c = (idx / 16) % 256, b = idx / 4096;
        const float* p = g_fbuf + (((size_t)(b * 256 + c) * 8 + 2 * h) * 8 + 2 * w);
        float v = fmaxf(fmaxf(p[0], p[1]), fmaxf(p[8], p[9]));
        g_qa[b * 4096 + (c * 16 + h * 4 + w)] = (unsigned char)quant_idx(v, s);
    }
}

__global__ void k_quant_act_fc(int slot) {
    float s = slot_scale(slot);
    int idx = blockIdx.x * blockDim.x + threadIdx.x;
    if (idx < BATCH * 4096) g_qa[idx] = (unsigned char)quant_idx(g_fbuf[idx], s);
}

// ------- LUT conv: 64 o-lanes x NC chunks; 12 Kahan chains (wp x kw) -------
template <int C, int O, int H, int W, int WT, int NC, bool QUANT>
__global__ void __launch_bounds__(64 * NC) k_conv(const float* __restrict__ lut,
                                                  const float* __restrict__ bias,
                                                  const float* __restrict__ fsrc,
                                                  int woff, int aslot, int wslot, int oslot) {
    constexpr int TW = WT + 4;   // 12 u16 = 24B rows, 8B-aligned
    constexpr int WP = WT / 2;   // 4 packed output pairs
    __shared__ float slut[256];
    __shared__ __align__(16) unsigned short sia[3 * C * TW];
    __shared__ u64 sred[(NC > 1 ? (NC - 1) * 64 * (2 * WP + 1) : 1)];
    const int lane_o = threadIdx.x;
    const int cc = threadIdx.y;
    const int tid = lane_o + 64 * cc;
    constexpr int NT = 64 * NC;
    const int o = blockIdx.x * 64 + lane_o;
    const int w0 = blockIdx.y * WT;
    const int b = blockIdx.z / H, h = blockIdx.z % H;

    for (int i = tid; i < 256; i += NT) slut[i] = lut[i];
    {
        float sa = QUANT ? slot_scale(aslot) : 0.0f;
        for (int i = tid; i < 3 * C * TW; i += NT) {
            int r = i / (C * TW), rem = i - r * C * TW, c = rem / TW, ww = rem - c * TW;
            int gh = h + r - 1, gw = w0 + ww - 1;
            unsigned int v = 8;  // quantized-zero level: padding goes through the LUT
            if (ww < WT + 2 && (unsigned)gh < (unsigned)H && (unsigned)gw < (unsigned)W) {
                if (QUANT)
                    v = quant_idx(fsrc[((size_t)(b * C + c) * H + gh) * W + gw], sa);
                else
                    v = g_qa[((b * H + gh) * C + c) * W + gw];
            }
            sia[i] = (unsigned short)(v << 6);
        }
    }
    __syncthreads();

    // 12 independent chains: index kw*WP + wp
    u64 acc2[3 * WP], cmp2[3 * WP];
#pragma unroll
    for (int i = 0; i < 3 * WP; ++i) { acc2[i] = 0ULL; cmp2[i] = 0ULL; }
    const uchar4* wq = reinterpret_cast<const uchar4*>(g_qw + woff) + o;
    const char* lb = reinterpret_cast<const char*>(slut);
    constexpr int CS = C / NC;
    const int cbeg = cc * CS;

    for (int c = cbeg; c < cbeg + CS; ++c) {
#pragma unroll
        for (int kh = 0; kh < 3; ++kh) {
            uchar4 wv = wq[(c * 3 + kh) * O];
            const ushort4* row4 = reinterpret_cast<const ushort4*>(&sia[(kh * C + c) * TW]);
            ushort4 q0 = row4[0], q1 = row4[1], q2 = row4[2];
            unsigned int rv[12] = {q0.x, q0.y, q0.z, q0.w, q1.x, q1.y,
                                   q1.z, q1.w, q2.x, q2.y, q2.z, q2.w};
            unsigned int woffs[3] = {wv.x, wv.y, wv.z};
#pragma unroll
            for (int kw = 0; kw < 3; ++kw)
#pragma unroll
                for (int wp = 0; wp < WP; ++wp) {
                    float v0 = *reinterpret_cast<const float*>(lb + (rv[2 * wp + kw] + woffs[kw]));
                    float v1 = *reinterpret_cast<const float*>(lb + (rv[2 * wp + 1 + kw] + woffs[kw]));
                    kahan2(acc2[kw * WP + wp], cmp2[kw * WP + wp], pack2(v0, v1));
                }
        }
    }
    // fold kw=1,2 chains into kw=0 chains (exact Kahan merge)
#pragma unroll
    for (int wp = 0; wp < WP; ++wp) {
#pragma unroll
        for (int kw = 1; kw < 3; ++kw) {
            kahan2(acc2[wp], cmp2[wp], acc2[kw * WP + wp]);
            kahan2(acc2[wp], cmp2[wp], NEG2(cmp2[kw * WP + wp]));
        }
    }

    if (NC > 1) {
        constexpr int STR = 2 * WP + 1;
        if (cc > 0) {
            u64* dp = &sred[((cc - 1) * 64 + lane_o) * STR];
#pragma unroll
            for (int i = 0; i < WP; ++i) { dp[i] = acc2[i]; dp[WP + i] = cmp2[i]; }
        }
        __syncthreads();
        if (cc == 0) {
#pragma unroll
            for (int i = 0; i < NC - 1; ++i) {
                const u64* sp = &sred[(i * 64 + lane_o) * STR];
#pragma unroll
                for (int wp = 0; wp < WP; ++wp) {
                    kahan2(acc2[wp], cmp2[wp], sp[wp]);
                    kahan2(acc2[wp], cmp2[wp], NEG2(sp[WP + wp]));
                }
            }
        }
    }

    if (cc == 0) {
        float sc = __fmul_rn(slot_scale(aslot), slot_scale(wslot));
        float bv = bias[o], m = 0.0f;
#pragma unroll
        for (int wp = 0; wp < WP; ++wp) {
            float a0, a1;
            unpack2(acc2[wp], a0, a1);
            float v0 = fmaxf(__fadd_rn(__fmul_rn(a0, sc), bv), 0.0f);
            float v1 = fmaxf(__fadd_rn(__fmul_rn(a1, sc), bv), 0.0f);
            size_t base = ((size_t)(b * O + o) * H + h) * W + w0 + 2 * wp;
            g_fbuf[base] = v0;
            g_fbuf[base + 1] = v1;
            m = fmaxf(m, fmaxf(v0, v1));
        }
#pragma unroll
        for (int off = 16; off; off >>= 1) m = fmaxf(m, __shfl_xor_sync(0xffffffffu, m, off));
        if ((lane_o & 31) == 0) atomicMax(&g_maxi[oslot], __float_as_int(m));
    }
}

// ------- LUT fc: OT o-lanes x NC f-chunks, 4 packed Kahan chains -------
template <int F, int OT, int NC, bool RELU>
__global__ void __launch_bounds__(OT * NC) k_fc(const float* __restrict__ lut,
                                                const float* __restrict__ bias, float* out_ext,
                                                int woff, int O, int aslot, int wslot, int oslot) {
    __shared__ float slut[256];
    __shared__ __align__(16) unsigned short sia[F];
    __shared__ float sred[(NC > 1 ? (NC - 1) * OT * 2 : 1)];
    const int lx = threadIdx.x, cc = threadIdx.y;
    const int tid = lx + OT * cc;
    constexpr int NT = OT * NC;
    const int b = blockIdx.y;
    for (int i = tid; i < 256; i += NT) slut[i] = lut[i];
    for (int f = tid; f < F; f += NT)
        sia[f] = (unsigned short)((unsigned int)g_qa[b * F + f] << 6);
    __syncthreads();

    const int o = blockIdx.x * OT + lx;
    const uchar4* wq = reinterpret_cast<const uchar4*>(g_qw + woff) + o;
    const char* lb = reinterpret_cast<const char*>(slut);
    constexpr int F4C = F / 4 / NC;
    u64 S[4] = {0ULL, 0ULL, 0ULL, 0ULL}, Cc[4] = {0ULL, 0ULL, 0ULL, 0ULL};
#pragma unroll 2
    for (int j = 0; j < F4C / 2; ++j) {
#pragma unroll
        for (int k = 0; k < 2; ++k) {
            int f4 = cc * F4C + j * 2 + k;
            uchar4 wv = wq[(size_t)f4 * O];
            ushort4 iv = *reinterpret_cast<const ushort4*>(&sia[f4 * 4]);
            float v0 = *reinterpret_cast<const float*>(lb + (iv.x + (unsigned int)wv.x));
            float v1 = *reinterpret_cast<const float*>(lb + (iv.y + (unsigned int)wv.y));
            float v2 = *reinterpret_cast<const float*>(lb + (iv.z + (unsigned int)wv.z));
            float v3 = *reinterpret_cast<const float*>(lb + (iv.w + (unsigned int)wv.w));
            kahan2(S[k * 2 + 0], Cc[k * 2 + 0], pack2(v0, v1));
            kahan2(S[k * 2 + 1], Cc[k * 2 + 1], pack2(v2, v3));
        }
    }
    // fold chains 1..3 into chain 0 (packed), then to scalar
#pragma unroll
    for (int k = 1; k < 4; ++k) {
        kahan2(S[0], Cc[0], S[k]);
        kahan2(S[0], Cc[0], NEG2(Cc[k]));
    }
    float s0, s0h, c0, c0h;
    unpack2(S[0], s0, s0h); unpack2(Cc[0], c0, c0h);
    kahan(s0, c0, s0h); kahan(s0, c0, -c0h);

    if (NC > 1) {
        if (cc > 0) {
            sred[(cc - 1) * OT * 2 + lx * 2 + 0] = s0;
            sred[(cc - 1) * OT * 2 + lx * 2 + 1] = c0;
        }
        __syncthreads();
        if (cc == 0) {
#pragma unroll
            for (int i = 0; i < NC - 1; ++i) {
                kahan(s0, c0, sred[i * OT * 2 + lx * 2 + 0]);
                kahan(s0, c0, -sred[i * OT * 2 + lx * 2 + 1]);
            }
        }
    }

    if (cc == 0) {
        float sc = __fmul_rn(slot_scale(aslot), slot_scale(wslot));
        float v = __fadd_rn(__fmul_rn(s0, sc), bias[o]);
        if (RELU) {
            v = fmaxf(v, 0.0f);
            g_fbuf[(size_t)b * O + o] = v;
            float m = v;
#pragma unroll
            for (int off = 16; off; off >>= 1) m = fmaxf(m, __shfl_xor_sync(0xffffffffu, m, off));
            if ((lx & 31) == 0) atomicMax(&g_maxi[oslot], __float_as_int(m));
        } else {
            out_ext[(size_t)b * O + o] = v;
        }
    }
}

__global__ void __launch_bounds__(320) k_fc_small(const float* __restrict__ lut,
                                                  const float* __restrict__ bias, float* out,
                                                  int woff, int aslot, int wslot) {
    __shared__ float slut[256];
    __shared__ __align__(16) unsigned short sia[4096];
    const int lane = threadIdx.x, o = threadIdx.y, b = blockIdx.x;
    const int tid = lane + 32 * o;
    for (int i = tid; i < 256; i += 320) slut[i] = lut[i];
    for (int f = tid; f < 4096; f += 320)
        sia[f] = (unsigned short)((unsigned int)g_qa[b * 4096 + f] << 6);
    __syncthreads();

    const uchar4* wq = reinterpret_cast<const uchar4*>(g_qw + woff) + o;
    const char* lb = reinterpret_cast<const char*>(slut);
    float s = 0.f, c = 0.f;
#pragma unroll 4
    for (int j = 0; j < 32; ++j) {
        int f4 = j * 32 + lane;
        uchar4 wv = wq[f4 * 10];
        ushort4 iv = *reinterpret_cast<const ushort4*>(&sia[f4 * 4]);
        kahan(s, c, *reinterpret_cast<const float*>(lb + (iv.x + (unsigned int)wv.x)));
        kahan(s, c, *reinterpret_cast<const float*>(lb + (iv.y + (unsigned int)wv.y)));
        kahan(s, c, *reinterpret_cast<const float*>(lb + (iv.z + (unsigned int)wv.z)));
        kahan(s, c, *reinterpret_cast<const float*>(lb + (iv.w + (unsigned int)wv.w)));
    }
#pragma unroll
    for (int off = 16; off; off >>= 1) {
        float ps = __shfl_xor_sync(0xffffffffu, s, off);
        float pc = __shfl_xor_sync(0xffffffffu, c, off);
        kahan(s, c, ps);
        kahan(s, c, -pc);
    }
    if (lane == 0) {
        float sc = __fmul_rn(slot_scale(aslot), slot_scale(wslot));
        out[b * 10 + o] = __fadd_rn(__fmul_rn(s, sc), bias[o]);
    }
}

extern "C" void kernel_launch(void* const* d_in, const int* in_sizes, int n_in,
                              void* d_out, int out_size) {
    const float* x = (const float*)d_in[0];
    const float* w[8]; const float* bb[8];
    for (int i = 0; i < 8; i++) { w[i] = (const float*)d_in[1 + 2 * i]; bb[i] = (const float*)d_in[2 + 2 * i]; }
    const float* luts = (const float*)d_in[17];
    float* out = (float*)d_out;

    k_init<<<1, 16>>>();

    AMaxArgs am;
    int wn[8] = {1728, 110592, 663552, 884736, 589824, 16777216, 16777216, 40960};
    am.b0[0] = 0;
    for (int i = 0; i < 8; i++) {
        am.p[i] = w[i]; am.n[i] = wn[i]; am.slot[i] = i;
        int bl = wn[i] / 8192; if (bl < 1) bl = 1; if (bl > 864) bl = 864;
        am.b0[i + 1] = am.b0[i] + bl;
    }
    am.p[8] = x; am.n[8] = 24576; am.slot[8] = 8;
    am.b0[9] = am.b0[8] + 3;
    k_absmax_all<<<am.b0[9], 256>>>(am);

    QWCArgs qc; for (int i = 0; i < 5; i++) qc.w[i] = w[i];
    k_qw_conv<<<(750144 + 255) / 256, 256>>>(qc);

    k_conv<3, 64, 32, 32, 8, 1, true><<<dim3(1, 4, 256), dim3(64, 1)>>>(
        luts + 0 * 256, bb[0], x, W0OFF, 8, 0, 9);
    k_pool_quant<<<512, 256>>>(64, 32, 32, 9);
    k_conv<64, 192, 16, 16, 8, 2, false><<<dim3(3, 2, 128), dim3(64, 2)>>>(
        luts + 1 * 256, bb[1], nullptr, W1OFF, 9, 1, 10);
    k_pool_quant<<<384, 256>>>(192, 16, 16, 10);
    k_conv<192, 384, 8, 8, 8, 4, false><<<dim3(6, 1, 64), dim3(64, 4)>>>(
        luts + 2 * 256, bb[2], nullptr, W2OFF, 10, 2, 11);
    k_quant_act<<<768, 256>>>(nullptr, 384, 8, 8, 11);
    k_conv<384, 256, 8, 8, 8, 6, false><<<dim3(4, 1, 64), dim3(64, 6)>>>(
        luts + 3 * 256, bb[3], nullptr, W3OFF, 11, 3, 12);
    k_quant_act<<<512, 256>>>(nullptr, 256, 8, 8, 12);
    k_conv<256, 256, 8, 8, 8, 4, false><<<dim3(4, 1, 64), dim3(64, 4)>>>(
        luts + 4 * 256, bb[4], nullptr, W4OFF, 12, 4, 13);
    k_pool_quant_fc<<<128, 256>>>(13);

    QWFArgs qf; qf.w[0] = w[5]; qf.w[1] = w[6]; qf.w[2] = w[7];
    k_qw_fc<<<dim3(32, 128, 3), 256>>>(qf);

    k_fc<4096, 128, 4, true><<<dim3(32, 8), dim3(128, 4)>>>(luts + 5 * 256, bb[5], nullptr, W5OFF, 4096, 13, 5, 14);
    k_quant_act_fc<<<128, 256>>>(14);
    k_fc<4096, 128, 4, true><<<dim3(32, 8), dim3(128, 4)>>>(luts + 6 * 256, bb[6], nullptr, W6OFF, 4096, 14, 6, 15);
    k_quant_act_fc<<<128, 256>>>(15);
    k_fc_small<<<8, dim3(32, 10)>>>(luts + 7 * 256, bb[7], out, W7OFF, 15, 7);
}

// round 16
// speedup vs baseline: 1.2258x; 1.0581x over previous
#include <cuda_runtime.h>

#define BATCH 8
typedef unsigned long long u64;

__device__ __align__(16) unsigned char g_qw[36595968];
__device__ __align__(16) unsigned char g_qa[262144];
__device__ __align__(16) float g_fbuf[524288];
// max bits: 0..7 = |w0..7|, 8 = |x|, 9..13 = conv0..4 out, 14/15 = fc5/6 out
__device__ int g_maxi[16];

#define W0OFF 0
#define W1OFF 2304
#define W2OFF 149760
#define W3OFF 1034496
#define W4OFF 2214144
#define W5OFF 3000576
#define W6OFF 19777792
#define W7OFF 36555008

__device__ __forceinline__ float slot_scale(int s) {
    return fmaxf(__fdiv_rn(__int_as_float(g_maxi[s]), 7.0f), 1e-8f);
}
__device__ __forceinline__ unsigned int quant_idx(float x, float s) {
    float q = rintf(__fdiv_rn(x, s));  // half-even, exact div
    q = fminf(fmaxf(q, -8.0f), 7.0f);
    return (unsigned int)((int)q + 8);
}
// fast path: mul-by-reciprocal; provably equals exact div unless within 1e-4 of
// a .5 boundary (error bound 1.7e-6 for |x/s|<=~8.5); near-ties take exact div.
__device__ __forceinline__ unsigned int quant_idx_fast(float x, float s, float rs) {
    float f = __fmul_rn(x, rs);
    float r = rintf(f);
    float d = fabsf(__fadd_rn(f, -r));
    if (fabsf(__fadd_rn(d, -0.5f)) < 1e-4f) r = rintf(__fdiv_rn(x, s));
    r = fminf(fmaxf(r, -8.0f), 7.0f);
    return (unsigned int)((int)r + 8);
}
__device__ __forceinline__ void kahan(float& s, float& c, float val) {
    float y = __fadd_rn(val, -c);
    float t = __fadd_rn(s, y);
    c = __fadd_rn(__fadd_rn(t, -s), -y);
    s = t;
}
__device__ __forceinline__ u64 pack2(float lo, float hi) {
    u64 v; asm("mov.b64 %0, {%1, %2};" : "=l"(v) : "f"(lo), "f"(hi)); return v;
}
__device__ __forceinline__ void unpack2(u64 v, float& lo, float& hi) {
    asm("mov.b64 {%0, %1}, %2;" : "=f"(lo), "=f"(hi) : "l"(v));
}
__device__ __forceinline__ void kahan2(u64& s, u64& c, u64 val) {
    u64 y, t, d;
    asm("sub.rn.f32x2 %0, %1, %2;" : "=l"(y) : "l"(val), "l"(c));
    asm("add.rn.f32x2 %0, %1, %2;" : "=l"(t) : "l"(s), "l"(y));
    asm("sub.rn.f32x2 %0, %1, %2;" : "=l"(d) : "l"(t), "l"(s));
    asm("sub.rn.f32x2 %0, %1, %2;" : "=l"(c) : "l"(d), "l"(y));
    s = t;
}
#define NEG2(v) ((v) ^ 0x8000000080000000ULL)

__global__ void k_init() { if (threadIdx.x < 16) g_maxi[threadIdx.x] = 0; }

struct AMaxArgs { const float* p[9]; int n[9]; int slot[9]; int b0[10]; };
__global__ void k_absmax_all(AMaxArgs a) {
    int seg = 0;
#pragma unroll
    for (int i = 1; i < 9; i++) if ((int)blockIdx.x >= a.b0[i]) seg = i;
    int lb = blockIdx.x - a.b0[seg], nb = a.b0[seg + 1] - a.b0[seg];
    const float4* p4 = (const float4*)a.p[seg];
    int n4 = a.n[seg] >> 2;
    float m = 0.0f;
    for (int i = lb * 256 + threadIdx.x; i < n4; i += nb * 256) {
        float4 v = p4[i];
        m = fmaxf(m, fmaxf(fmaxf(fabsf(v.x), fabsf(v.y)), fmaxf(fabsf(v.z), fabsf(v.w))));
    }
#pragma unroll
    for (int o = 16; o; o >>= 1) m = fmaxf(m, __shfl_xor_sync(0xffffffffu, m, o));
    if ((threadIdx.x & 31) == 0) atomicMax(&g_maxi[a.slot[seg]], __float_as_int(m));
}

struct QWCArgs { const float* w[5]; };
__global__ void k_qw_conv(QWCArgs a) {
    const int OA[5] = {64, 192, 384, 256, 256}, CA[5] = {3, 64, 192, 384, 256};
    const int WO[5] = {W0OFF, W1OFF, W2OFF, W3OFF, W4OFF};
    const int BASE[6] = {0, 576, 37440, 258624, 553536, 750144};
    int idx = blockIdx.x * blockDim.x + threadIdx.x;
    if (idx >= 750144) return;
    int l = 0;
#pragma unroll
    for (int i = 1; i < 5; i++) if (idx >= BASE[i]) l = i;
    int li = idx - BASE[l], O = OA[l], C = CA[l];
    float s = slot_scale(l), rs = __frcp_rn(s);
    int o = li % O, ckh = li / O, c = ckh / 3, kh = ckh % 3;
    const float* src = a.w[l] + ((size_t)(o * C + c) * 3 + kh) * 3;
    uchar4 v;
    v.x = (unsigned char)(quant_idx_fast(src[0], s, rs) << 2);
    v.y = (unsigned char)(quant_idx_fast(src[1], s, rs) << 2);
    v.z = (unsigned char)(quant_idx_fast(src[2], s, rs) << 2);
    v.w = 0;
    reinterpret_cast<uchar4*>(g_qw + WO[l])[(size_t)ckh * O + o] = v;
}

// fused fc weight quant: in-register uchar4 pack, uint32 smem tile (no byte-STS)
struct QWFArgs { const float* w[3]; };
__global__ void k_qw_fc(QWFArgs a) {
    const int OA[3] = {4096, 4096, 10};
    const int WO[3] = {W5OFF, W6OFF, W7OFF};
    const int z = blockIdx.z, F = 4096, O = OA[z];
    __shared__ unsigned int t32[32][33];
    float s = slot_scale(5 + z), rs = __frcp_rn(s);
    int f0 = blockIdx.x * 128, o0 = blockIdx.y * 32;
    if (o0 >= O) return;
    const float* w = a.w[z];
    // lanes vary f4l -> coalesced float4 reads; pack uchar4 in-register
    for (int i = threadIdx.x; i < 32 * 32; i += blockDim.x) {
        int f4l = i & 31, ol = i >> 5, o = o0 + ol;
        unsigned int packed = 0;
        if (o < O) {
            float4 wv4 = *reinterpret_cast<const float4*>(&w[(size_t)o * F + f0 + f4l * 4]);
            packed = (quant_idx_fast(wv4.x, s, rs) << 2)
                   | ((quant_idx_fast(wv4.y, s, rs) << 2) << 8)
                   | ((quant_idx_fast(wv4.z, s, rs) << 2) << 16)
                   | ((quant_idx_fast(wv4.w, s, rs) << 2) << 24);
        }
        t32[f4l][ol] = packed;
    }
    __syncthreads();
    for (int i = threadIdx.x; i < 32 * 32; i += blockDim.x) {
        int f4l = i >> 5, ol = i & 31, o = o0 + ol;
        if (o >= O) continue;
        reinterpret_cast<unsigned int*>(g_qw + WO[z])[(size_t)(f0 / 4 + f4l) * O + o] =
            t32[f4l][ol];
    }
}

__global__ void k_quant_act(const float* in, int C, int H, int W, int slot) {
    const float* src = in ? in : g_fbuf;
    int n = BATCH * C * H * W;
    float s = slot_scale(slot), rs = __frcp_rn(s);
    for (int idx = blockIdx.x * blockDim.x + threadIdx.x; idx < n; idx += gridDim.x * blockDim.x) {
        int w = idx % W, t = idx / W, h = t % H; t /= H;
        int c = t % C, b = t / C;
        g_qa[((b * H + h) * C + c) * W + w] = (unsigned char)quant_idx_fast(src[idx], s, rs);
    }
}

__global__ void k_pool_quant(int C, int H, int W, int slot) {
    int H2 = H >> 1, W2 = W >> 1, n = BATCH * C * H2 * W2;
    float s = slot_scale(slot), rs = __frcp_rn(s);
    for (int idx = blockIdx.x * blockDim.x + threadIdx.x; idx < n; idx += gridDim.x * blockDim.x) {
        int w = idx % W2, t = idx / W2, h = t % H2; t /= H2;
        int c = t % C, b = t / C;
        const float* p = g_fbuf + (((size_t)(b * C + c) * H + 2 * h) * W + 2 * w);
        float v = fmaxf(fmaxf(p[0], p[1]), fmaxf(p[W], p[W + 1]));
        g_qa[((b * H2 + h) * C + c) * W2 + w] = (unsigned char)quant_idx_fast(v, s, rs);
    }
}

__global__ void k_pool_quant_fc(int slot) {
    int n = BATCH * 4096;
    float s = slot_scale(slot), rs = __frcp_rn(s);
    for (int idx = blockIdx.x * blockDim.x + threadIdx.x; idx < n; idx += gridDim.x * blockDim.x) {
        int w = idx % 4, h = (idx / 4) % 4, c = (idx / 16) % 256, b = idx / 4096;
        const float* p = g_fbuf + (((size_t)(b * 256 + c) * 8 + 2 * h) * 8 + 2 * w);
        float v = fmaxf(fmaxf(p[0], p[1]), fmaxf(p[8], p[9]));
        g_qa[b * 4096 + (c * 16 + h * 4 + w)] = (unsigned char)quant_idx_fast(v, s, rs);
    }
}

__global__ void k_quant_act_fc(int slot) {
    float s = slot_scale(slot), rs = __frcp_rn(s);
    int idx = blockIdx.x * blockDim.x + threadIdx.x;
    if (idx < BATCH * 4096) g_qa[idx] = (unsigned char)quant_idx_fast(g_fbuf[idx], s, rs);
}

// ------- LUT conv: LANES o-lanes x NC chunks; 12 Kahan chains (wp x kw) -------
template <int C, int O, int H, int W, int WT, int LANES, int NC, bool QUANT>
__global__ void __launch_bounds__(LANES * NC) k_conv(const float* __restrict__ lut,
                                                     const float* __restrict__ bias,
                                                     const float* __restrict__ fsrc,
                                                     int woff, int aslot, int wslot, int oslot) {
    constexpr int TW = WT + 4;   // 12 u16 = 24B rows, ushort4-aligned
    constexpr int WP = WT / 2;
    __shared__ float slut[256];
    __shared__ __align__(16) unsigned short sia[3 * C * TW];
    __shared__ u64 sred[(NC > 1 ? (NC - 1) * LANES * (2 * WP + 1) : 1)];
    const int lane_o = threadIdx.x;
    const int cc = threadIdx.y;
    const int tid = lane_o + LANES * cc;
    constexpr int NT = LANES * NC;
    const int o = blockIdx.x * LANES + lane_o;
    const int w0 = blockIdx.y * WT;
    const int b = blockIdx.z / H, h = blockIdx.z % H;

    for (int i = tid; i < 256; i += NT) slut[i] = lut[i];
    {
        float sa = QUANT ? slot_scale(aslot) : 0.0f;
        float rsa = QUANT ? __frcp_rn(sa) : 0.0f;
        for (int i = tid; i < 3 * C * TW; i += NT) {
            int r = i / (C * TW), rem = i - r * C * TW, c = rem / TW, ww = rem - c * TW;
            int gh = h + r - 1, gw = w0 + ww - 1;
            unsigned int v = 8;  // quantized-zero level: padding goes through the LUT
            if (ww < WT + 2 && (unsigned)gh < (unsigned)H && (unsigned)gw < (unsigned)W) {
                if (QUANT)
                    v = quant_idx_fast(fsrc[((size_t)(b * C + c) * H + gh) * W + gw], sa, rsa);
                else
                    v = g_qa[((b * H + gh) * C + c) * W + gw];
            }
            sia[i] = (unsigned short)(v << 6);
        }
    }
    __syncthreads();

    u64 acc2[3 * WP], cmp2[3 * WP];
#pragma unroll
    for (int i = 0; i < 3 * WP; ++i) { acc2[i] = 0ULL; cmp2[i] = 0ULL; }
    const uchar4* wq = reinterpret_cast<const uchar4*>(g_qw + woff) + o;
    const char* lb = reinterpret_cast<const char*>(slut);
    constexpr int CS = C / NC;
    const int cbeg = cc * CS;

    for (int c = cbeg; c < cbeg + CS; ++c) {
#pragma unroll
        for (int kh = 0; kh < 3; ++kh) {
            uchar4 wv = wq[(c * 3 + kh) * O];
            const ushort4* row4 = reinterpret_cast<const ushort4*>(&sia[(kh * C + c) * TW]);
            ushort4 q0 = row4[0], q1 = row4[1], q2 = row4[2];
            unsigned int rv[12] = {q0.x, q0.y, q0.z, q0.w, q1.x, q1.y,
                                   q1.z, q1.w, q2.x, q2.y, q2.z, q2.w};
            unsigned int woffs[3] = {wv.x, wv.y, wv.z};
#pragma unroll
            for (int kw = 0; kw < 3; ++kw)
#pragma unroll
                for (int wp = 0; wp < WP; ++wp) {
                    float v0 = *reinterpret_cast<const float*>(lb + (rv[2 * wp + kw] + woffs[kw]));
                    float v1 = *reinterpret_cast<const float*>(lb + (rv[2 * wp + 1 + kw] + woffs[kw]));
                    kahan2(acc2[kw * WP + wp], cmp2[kw * WP + wp], pack2(v0, v1));
                }
        }
    }
#pragma unroll
    for (int wp = 0; wp < WP; ++wp) {
#pragma unroll
        for (int kw = 1; kw < 3; ++kw) {
            kahan2(acc2[wp], cmp2[wp], acc2[kw * WP + wp]);
            kahan2(acc2[wp], cmp2[wp], NEG2(cmp2[kw * WP + wp]));
        }
    }

    if (NC > 1) {
        constexpr int STR = 2 * WP + 1;
        if (cc > 0) {
            u64* dp = &sred[((cc - 1) * LANES + lane_o) * STR];
#pragma unroll
            for (int i = 0; i < WP; ++i) { dp[i] = acc2[i]; dp[WP + i] = cmp2[i]; }
        }
        __syncthreads();
        if (cc == 0) {
#pragma unroll
            for (int i = 0; i < NC - 1; ++i) {
                const u64* sp = &sred[(i * LANES + lane_o) * STR];
#pragma unroll
                for (int wp = 0; wp < WP; ++wp) {
                    kahan2(acc2[wp], cmp2[wp], sp[wp]);
                    kahan2(acc2[wp], cmp2[wp], NEG2(sp[WP + wp]));
                }
            }
        }
    }

    if (cc == 0) {
        float sc = __fmul_rn(slot_scale(aslot), slot_scale(wslot));
        float bv = bias[o], m = 0.0f;
#pragma unroll
        for (int wp = 0; wp < WP; ++wp) {
            float a0, a1;
            unpack2(acc2[wp], a0, a1);
            float v0 = fmaxf(__fadd_rn(__fmul_rn(a0, sc), bv), 0.0f);
            float v1 = fmaxf(__fadd_rn(__fmul_rn(a1, sc), bv), 0.0f);
            size_t base = ((size_t)(b * O + o) * H + h) * W + w0 + 2 * wp;
            g_fbuf[base] = v0;
            g_fbuf[base + 1] = v1;
            m = fmaxf(m, fmaxf(v0, v1));
        }
#pragma unroll
        for (int off = 16; off; off >>= 1) m = fmaxf(m, __shfl_xor_sync(0xffffffffu, m, off));
        if ((lane_o & 31) == 0) atomicMax(&g_maxi[oslot], __float_as_int(m));
    }
}

// ------- LUT fc: OT o-lanes x NC f-chunks, 4 packed Kahan chains -------
template <int F, int OT, int NC, bool RELU>
__global__ void __launch_bounds__(OT * NC) k_fc(const float* __restrict__ lut,
                                                const float* __restrict__ bias, float* out_ext,
                                                int woff, int O, int aslot, int wslot, int oslot) {
    __shared__ float slut[256];
    __shared__ __align__(16) unsigned short sia[F];
    __shared__ float sred[(NC > 1 ? (NC - 1) * OT * 2 : 1)];
    const int lx = threadIdx.x, cc = threadIdx.y;
    const int tid = lx + OT * cc;
    constexpr int NT = OT * NC;
    const int b = blockIdx.y;
    for (int i = tid; i < 256; i += NT) slut[i] = lut[i];
    for (int f = tid; f < F; f += NT)
        sia[f] = (unsigned short)((unsigned int)g_qa[b * F + f] << 6);
    __syncthreads();

    const int o = blockIdx.x * OT + lx;
    const uchar4* wq = reinterpret_cast<const uchar4*>(g_qw + woff) + o;
    const char* lb = reinterpret_cast<const char*>(slut);
    constexpr int F4C = F / 4 / NC;
    u64 S[4] = {0ULL, 0ULL, 0ULL, 0ULL}, Cc[4] = {0ULL, 0ULL, 0ULL, 0ULL};
#pragma unroll 2
    for (int j = 0; j < F4C / 2; ++j) {
#pragma unroll
        for (int k = 0; k < 2; ++k) {
            int f4 = cc * F4C + j * 2 + k;
            uchar4 wv = wq[(size_t)f4 * O];
            ushort4 iv = *reinterpret_cast<const ushort4*>(&sia[f4 * 4]);
            float v0 = *reinterpret_cast<const float*>(lb + (iv.x + (unsigned int)wv.x));
            float v1 = *reinterpret_cast<const float*>(lb + (iv.y + (unsigned int)wv.y));
            float v2 = *reinterpret_cast<const float*>(lb + (iv.z + (unsigned int)wv.z));
            float v3 = *reinterpret_cast<const float*>(lb + (iv.w + (unsigned int)wv.w));
            kahan2(S[k * 2 + 0], Cc[k * 2 + 0], pack2(v0, v1));
            kahan2(S[k * 2 + 1], Cc[k * 2 + 1], pack2(v2, v3));
        }
    }
#pragma unroll
    for (int k = 1; k < 4; ++k) {
        kahan2(S[0], Cc[0], S[k]);
        kahan2(S[0], Cc[0], NEG2(Cc[k]));
    }
    float s0, s0h, c0, c0h;
    unpack2(S[0], s0, s0h); unpack2(Cc[0], c0, c0h);
    kahan(s0, c0, s0h); kahan(s0, c0, -c0h);

    if (NC > 1) {
        if (cc > 0) {
            sred[(cc - 1) * OT * 2 + lx * 2 + 0] = s0;
            sred[(cc - 1) * OT * 2 + lx * 2 + 1] = c0;
        }
        __syncthreads();
        if (cc == 0) {
#pragma unroll
            for (int i = 0; i < NC - 1; ++i) {
                kahan(s0, c0, sred[i * OT * 2 + lx * 2 + 0]);
                kahan(s0, c0, -sred[i * OT * 2 + lx * 2 + 1]);
            }
        }
    }

    if (cc == 0) {
        float sc = __fmul_rn(slot_scale(aslot), slot_scale(wslot));
        float v = __fadd_rn(__fmul_rn(s0, sc), bias[o]);
        if (RELU) {
            v = fmaxf(v, 0.0f);
            g_fbuf[(size_t)b * O + o] = v;
            float m = v;
#pragma unroll
            for (int off = 16; off; off >>= 1) m = fmaxf(m, __shfl_xor_sync(0xffffffffu, m, off));
            if ((lx & 31) == 0) atomicMax(&g_maxi[oslot], __float_as_int(m));
        } else {
            out_ext[(size_t)b * O + o] = v;
        }
    }
}

__global__ void __launch_bounds__(320) k_fc_small(const float* __restrict__ lut,
                                                  const float* __restrict__ bias, float* out,
                                                  int woff, int aslot, int wslot) {
    __shared__ float slut[256];
    __shared__ __align__(16) unsigned short sia[4096];
    const int lane = threadIdx.x, o = threadIdx.y, b = blockIdx.x;
    const int tid = lane + 32 * o;
    for (int i = tid; i < 256; i += 320) slut[i] = lut[i];
    for (int f = tid; f < 4096; f += 320)
        sia[f] = (unsigned short)((unsigned int)g_qa[b * 4096 + f] << 6);
    __syncthreads();

    const uchar4* wq = reinterpret_cast<const uchar4*>(g_qw + woff) + o;
    const char* lb = reinterpret_cast<const char*>(slut);
    float s = 0.f, c = 0.f;
#pragma unroll 4
    for (int j = 0; j < 32; ++j) {
        int f4 = j * 32 + lane;
        uchar4 wv = wq[f4 * 10];
        ushort4 iv = *reinterpret_cast<const ushort4*>(&sia[f4 * 4]);
        kahan(s, c, *reinterpret_cast<const float*>(lb + (iv.x + (unsigned int)wv.x)));
        kahan(s, c, *reinterpret_cast<const float*>(lb + (iv.y + (unsigned int)wv.y)));
        kahan(s, c, *reinterpret_cast<const float*>(lb + (iv.z + (unsigned int)wv.z)));
        kahan(s, c, *reinterpret_cast<const float*>(lb + (iv.w + (unsigned int)wv.w)));
    }
#pragma unroll
    for (int off = 16; off; off >>= 1) {
        float ps = __shfl_xor_sync(0xffffffffu, s, off);
        float pc = __shfl_xor_sync(0xffffffffu, c, off);
        kahan(s, c, ps);
        kahan(s, c, -pc);
    }
    if (lane == 0) {
        float sc = __fmul_rn(slot_scale(aslot), slot_scale(wslot));
        out[b * 10 + o] = __fadd_rn(__fmul_rn(s, sc), bias[o]);
    }
}

extern "C" void kernel_launch(void* const* d_in, const int* in_sizes, int n_in,
                              void* d_out, int out_size) {
    const float* x = (const float*)d_in[0];
    const float* w[8]; const float* bb[8];
    for (int i = 0; i < 8; i++) { w[i] = (const float*)d_in[1 + 2 * i]; bb[i] = (const float*)d_in[2 + 2 * i]; }
    const float* luts = (const float*)d_in[17];
    float* out = (float*)d_out;

    k_init<<<1, 16>>>();

    AMaxArgs am;
    int wn[8] = {1728, 110592, 663552, 884736, 589824, 16777216, 16777216, 40960};
    am.b0[0] = 0;
    for (int i = 0; i < 8; i++) {
        am.p[i] = w[i]; am.n[i] = wn[i]; am.slot[i] = i;
        int bl = wn[i] / 8192; if (bl < 1) bl = 1; if (bl > 864) bl = 864;
        am.b0[i + 1] = am.b0[i] + bl;
    }
    am.p[8] = x; am.n[8] = 24576; am.slot[8] = 8;
    am.b0[9] = am.b0[8] + 3;
    k_absmax_all<<<am.b0[9], 256>>>(am);

    QWCArgs qc; for (int i = 0; i < 5; i++) qc.w[i] = w[i];
    k_qw_conv<<<(750144 + 255) / 256, 256>>>(qc);

    k_conv<3, 64, 32, 32, 8, 64, 1, true><<<dim3(1, 4, 256), dim3(64, 1)>>>(
        luts + 0 * 256, bb[0], x, W0OFF, 8, 0, 9);
    k_pool_quant<<<512, 256>>>(64, 32, 32, 9);
    k_conv<64, 192, 16, 16, 8, 64, 4, false><<<dim3(3, 2, 128), dim3(64, 4)>>>(
        luts + 1 * 256, bb[1], nullptr, W1OFF, 9, 1, 10);
    k_pool_quant<<<384, 256>>>(192, 16, 16, 10);
    k_conv<192, 384, 8, 8, 8, 64, 8, false><<<dim3(6, 1, 64), dim3(64, 8)>>>(
        luts + 2 * 256, bb[2], nullptr, W2OFF, 10, 2, 11);
    k_quant_act<<<768, 256>>>(nullptr, 384, 8, 8, 11);
    k_conv<384, 256, 8, 8, 8, 32, 8, false><<<dim3(8, 1, 64), dim3(32, 8)>>>(
        luts + 3 * 256, bb[3], nullptr, W3OFF, 11, 3, 12);
    k_quant_act<<<512, 256>>>(nullptr, 256, 8, 8, 12);
    k_conv<256, 256, 8, 8, 8, 32, 8, false><<<dim3(8, 1, 64), dim3(32, 8)>>>(
        luts + 4 * 256, bb[4], nullptr, W4OFF, 12, 4, 13);
    k_pool_quant_fc<<<128, 256>>>(13);

    QWFArgs qf; qf.w[0] = w[5]; qf.w[1] = w[6]; qf.w[2] = w[7];
    k_qw_fc<<<dim3(32, 128, 3), 256>>>(qf);

    k_fc<4096, 128, 8, true><<<dim3(32, 8), dim3(128, 8)>>>(luts + 5 * 256, bb[5], nullptr, W5OFF, 4096, 13, 5, 14);
    k_quant_act_fc<<<128, 256>>>(14);
    k_fc<4096, 128, 8, true><<<dim3(32, 8), dim3(128, 8)>>>(luts + 6 * 256, bb[6], nullptr, W6OFF, 4096, 14, 6, 15);
    k_quant_act_fc<<<128, 256>>>(15);
    k_fc_small<<<8, dim3(32, 10)>>>(luts + 7 * 256, bb[7], out, W7OFF, 15, 7);
}

// round 17
// speedup vs baseline: 1.5168x; 1.2374x over previous
#include <cuda_runtime.h>

#define BATCH 8
typedef unsigned long long u64;
typedef long long s64;

__device__ __align__(16) unsigned char g_qw[36595968];
__device__ __align__(16) unsigned char g_qa[262144];
__device__ __align__(16) float g_fbuf[524288];
// max bits: 0..7 = |w0..7|, 8 = |x|, 9..13 = conv0..4 out, 14/15 = fc5/6 out
__device__ int g_maxi[16];

#define W0OFF 0
#define W1OFF 2304
#define W2OFF 149760
#define W3OFF 1034496
#define W4OFF 2214144
#define W5OFF 3000576
#define W6OFF 19777792
#define W7OFF 36555008

#define FIXS 2097152.0f           // 2^21
#define FIXR (1.0 / 2097152.0)    // exact pow-2

__device__ __forceinline__ float slot_scale(int s) {
    return fmaxf(__fdiv_rn(__int_as_float(g_maxi[s]), 7.0f), 1e-8f);
}
__device__ __forceinline__ unsigned int quant_idx(float x, float s) {
    float q = rintf(__fdiv_rn(x, s));  // half-even, exact div
    q = fminf(fmaxf(q, -8.0f), 7.0f);
    return (unsigned int)((int)q + 8);
}
// fast path: mul-by-reciprocal; equals exact div unless within 1e-4 of a .5
// boundary (error bound 1.7e-6 for |x/s|<=~8.5); near-ties take exact div.
__device__ __forceinline__ unsigned int quant_idx_fast(float x, float s, float rs) {
    float f = __fmul_rn(x, rs);
    float r = rintf(f);
    float d = fabsf(__fadd_rn(f, -r));
    if (fabsf(__fadd_rn(d, -0.5f)) < 1e-4f) r = rintf(__fdiv_rn(x, s));
    r = fminf(fmaxf(r, -8.0f), 7.0f);
    return (unsigned int)((int)r + 8);
}

__global__ void k_init() { if (threadIdx.x < 16) g_maxi[threadIdx.x] = 0; }

struct AMaxArgs { const float* p[9]; int n[9]; int slot[9]; int b0[10]; };
__global__ void k_absmax_all(AMaxArgs a) {
    int seg = 0;
#pragma unroll
    for (int i = 1; i < 9; i++) if ((int)blockIdx.x >= a.b0[i]) seg = i;
    int lb = blockIdx.x - a.b0[seg], nb = a.b0[seg + 1] - a.b0[seg];
    const float4* p4 = (const float4*)a.p[seg];
    int n4 = a.n[seg] >> 2;
    float m = 0.0f;
    for (int i = lb * 256 + threadIdx.x; i < n4; i += nb * 256) {
        float4 v = p4[i];
        m = fmaxf(m, fmaxf(fmaxf(fabsf(v.x), fabsf(v.y)), fmaxf(fabsf(v.z), fabsf(v.w))));
    }
#pragma unroll
    for (int o = 16; o; o >>= 1) m = fmaxf(m, __shfl_xor_sync(0xffffffffu, m, o));
    if ((threadIdx.x & 31) == 0) atomicMax(&g_maxi[a.slot[seg]], __float_as_int(m));
}

struct QWCArgs { const float* w[5]; };
__global__ void k_qw_conv(QWCArgs a) {
    const int OA[5] = {64, 192, 384, 256, 256}, CA[5] = {3, 64, 192, 384, 256};
    const int WO[5] = {W0OFF, W1OFF, W2OFF, W3OFF, W4OFF};
    const int BASE[6] = {0, 576, 37440, 258624, 553536, 750144};
    int idx = blockIdx.x * blockDim.x + threadIdx.x;
    if (idx >= 750144) return;
    int l = 0;
#pragma unroll
    for (int i = 1; i < 5; i++) if (idx >= BASE[i]) l = i;
    int li = idx - BASE[l], O = OA[l], C = CA[l];
    float s = slot_scale(l), rs = __frcp_rn(s);
    int o = li % O, ckh = li / O, c = ckh / 3, kh = ckh % 3;
    const float* src = a.w[l] + ((size_t)(o * C + c) * 3 + kh) * 3;
    uchar4 v;
    v.x = (unsigned char)(quant_idx_fast(src[0], s, rs) << 2);
    v.y = (unsigned char)(quant_idx_fast(src[1], s, rs) << 2);
    v.z = (unsigned char)(quant_idx_fast(src[2], s, rs) << 2);
    v.w = 0;
    reinterpret_cast<uchar4*>(g_qw + WO[l])[(size_t)ckh * O + o] = v;
}

struct QWFArgs { const float* w[3]; };
__global__ void k_qw_fc(QWFArgs a) {
    const int OA[3] = {4096, 4096, 10};
    const int WO[3] = {W5OFF, W6OFF, W7OFF};
    const int z = blockIdx.z, F = 4096, O = OA[z];
    __shared__ unsigned int t32[32][33];
    float s = slot_scale(5 + z), rs = __frcp_rn(s);
    int f0 = blockIdx.x * 128, o0 = blockIdx.y * 32;
    if (o0 >= O) return;
    const float* w = a.w[z];
    for (int i = threadIdx.x; i < 32 * 32; i += blockDim.x) {
        int f4l = i & 31, ol = i >> 5, o = o0 + ol;
        unsigned int packed = 0;
        if (o < O) {
            float4 wv4 = *reinterpret_cast<const float4*>(&w[(size_t)o * F + f0 + f4l * 4]);
            packed = (quant_idx_fast(wv4.x, s, rs) << 2)
                   | ((quant_idx_fast(wv4.y, s, rs) << 2) << 8)
                   | ((quant_idx_fast(wv4.z, s, rs) << 2) << 16)
                   | ((quant_idx_fast(wv4.w, s, rs) << 2) << 24);
        }
        t32[f4l][ol] = packed;
    }
    __syncthreads();
    for (int i = threadIdx.x; i < 32 * 32; i += blockDim.x) {
        int f4l = i >> 5, ol = i & 31, o = o0 + ol;
        if (o >= O) continue;
        reinterpret_cast<unsigned int*>(g_qw + WO[z])[(size_t)(f0 / 4 + f4l) * O + o] =
            t32[f4l][ol];
    }
}

__global__ void k_quant_act(const float* in, int C, int H, int W, int slot) {
    const float* src = in ? in : g_fbuf;
    int n = BATCH * C * H * W;
    float s = slot_scale(slot), rs = __frcp_rn(s);
    for (int idx = blockIdx.x * blockDim.x + threadIdx.x; idx < n; idx += gridDim.x * blockDim.x) {
        int w = idx % W, t = idx / W, h = t % H; t /= H;
        int c = t % C, b = t / C;
        g_qa[((b * H + h) * C + c) * W + w] = (unsigned char)quant_idx_fast(src[idx], s, rs);
    }
}

__global__ void k_pool_quant(int C, int H, int W, int slot) {
    int H2 = H >> 1, W2 = W >> 1, n = BATCH * C * H2 * W2;
    float s = slot_scale(slot), rs = __frcp_rn(s);
    for (int idx = blockIdx.x * blockDim.x + threadIdx.x; idx < n; idx += gridDim.x * blockDim.x) {
        int w = idx % W2, t = idx / W2, h = t % H2; t /= H2;
        int c = t % C, b = t / C;
        const float* p = g_fbuf + (((size_t)(b * C + c) * H + 2 * h) * W + 2 * w);
        float v = fmaxf(fmaxf(p[0], p[1]), fmaxf(p[W], p[W + 1]));
        g_qa[((b * H2 + h) * C + c) * W2 + w] = (unsigned char)quant_idx_fast(v, s, rs);
    }
}

__global__ void k_pool_quant_fc(int slot) {
    int n = BATCH * 4096;
    float s = slot_scale(slot), rs = __frcp_rn(s);
    for (int idx = blockIdx.x * blockDim.x + threadIdx.x; idx < n; idx += gridDim.x * blockDim.x) {
        int w = idx % 4, h = (idx / 4) % 4, c = (idx / 16) % 256, b = idx / 4096;
        const float* p = g_fbuf + (((size_t)(b * 256 + c) * 8 + 2 * h) * 8 + 2 * w);
        float v = fmaxf(fmaxf(p[0], p[1]), fmaxf(p[8], p[9]));
        g_qa[b * 4096 + (c * 16 + h * 4 + w)] = (unsigned char)quant_idx_fast(v, s, rs);
    }
}

__global__ void k_quant_act_fc(int slot) {
    float s = slot_scale(slot), rs = __frcp_rn(s);
    int idx = blockIdx.x * blockDim.x + threadIdx.x;
    if (idx < BATCH * 4096) g_qa[idx] = (unsigned char)quant_idx_fast(g_fbuf[idx], s, rs);
}

// ------- LUT conv: fixed-point int accumulation (exact), LANES x NC -------
// per c: each output accumulates 9 taps in int32 (max 9*66*2^21 = 1.25e9, safe),
// then widens into int64. All merges are exact integer adds.
template <int C, int O, int H, int W, int WT, int LANES, int NC, bool QUANT>
__global__ void __launch_bounds__(LANES * NC) k_conv(const float* __restrict__ lut,
                                                     const float* __restrict__ bias,
                                                     const float* __restrict__ fsrc,
                                                     int woff, int aslot, int wslot, int oslot) {
    constexpr int TW = WT + 4;
    __shared__ int slut_i[256];
    __shared__ __align__(16) unsigned short sia[3 * C * TW];
    __shared__ s64 sred[(NC > 1 ? (NC - 1) * LANES * WT : 1)];
    const int lane_o = threadIdx.x;
    const int cc = threadIdx.y;
    const int tid = lane_o + LANES * cc;
    constexpr int NT = LANES * NC;
    const int o = blockIdx.x * LANES + lane_o;
    const int w0 = blockIdx.y * WT;
    const int b = blockIdx.z / H, h = blockIdx.z % H;

    for (int i = tid; i < 256; i += NT)
        slut_i[i] = __float2int_rn(__fmul_rn(lut[i], FIXS));  // pow-2 scale: exact mul
    {
        float sa = QUANT ? slot_scale(aslot) : 0.0f;
        float rsa = QUANT ? __frcp_rn(sa) : 0.0f;
        for (int i = tid; i < 3 * C * TW; i += NT) {
            int r = i / (C * TW), rem = i - r * C * TW, c = rem / TW, ww = rem - c * TW;
            int gh = h + r - 1, gw = w0 + ww - 1;
            unsigned int v = 8;  // quantized-zero level: padding goes through the LUT
            if (ww < WT + 2 && (unsigned)gh < (unsigned)H && (unsigned)gw < (unsigned)W) {
                if (QUANT)
                    v = quant_idx_fast(fsrc[((size_t)(b * C + c) * H + gh) * W + gw], sa, rsa);
                else
                    v = g_qa[((b * H + gh) * C + c) * W + gw];
            }
            sia[i] = (unsigned short)(v << 6);
        }
    }
    __syncthreads();

    s64 tot[WT];
#pragma unroll
    for (int i = 0; i < WT; ++i) tot[i] = 0;
    const uchar4* wq = reinterpret_cast<const uchar4*>(g_qw + woff) + o;
    const char* lb = reinterpret_cast<const char*>(slut_i);
    constexpr int CS = C / NC;
    const int cbeg = cc * CS;

    for (int c = cbeg; c < cbeg + CS; ++c) {
        int p32[WT];
#pragma unroll
        for (int i = 0; i < WT; ++i) p32[i] = 0;
#pragma unroll
        for (int kh = 0; kh < 3; ++kh) {
            uchar4 wv = wq[(c * 3 + kh) * O];
            const ushort4* row4 = reinterpret_cast<const ushort4*>(&sia[(kh * C + c) * TW]);
            ushort4 q0 = row4[0], q1 = row4[1], q2 = row4[2];
            unsigned int rv[12] = {q0.x, q0.y, q0.z, q0.w, q1.x, q1.y,
                                   q1.z, q1.w, q2.x, q2.y, q2.z, q2.w};
            unsigned int woffs[3] = {wv.x, wv.y, wv.z};
#pragma unroll
            for (int kw = 0; kw < 3; ++kw)
#pragma unroll
                for (int w = 0; w < WT; ++w)
                    p32[w] += *reinterpret_cast<const int*>(lb + (rv[w + kw] + woffs[kw]));
        }
#pragma unroll
        for (int w = 0; w < WT; ++w) tot[w] += (s64)p32[w];
    }

    if (NC > 1) {
        if (cc > 0) {
            s64* dp = &sred[((cc - 1) * LANES + lane_o) * WT];
#pragma unroll
            for (int i = 0; i < WT; ++i) dp[i] = tot[i];
        }
        __syncthreads();
        if (cc == 0) {
#pragma unroll
            for (int i = 0; i < NC - 1; ++i) {
                const s64* sp = &sred[(i * LANES + lane_o) * WT];
#pragma unroll
                for (int w = 0; w < WT; ++w) tot[w] += sp[w];
            }
        }
    }

    if (cc == 0) {
        float sc = __fmul_rn(slot_scale(aslot), slot_scale(wslot));
        float bv = bias[o], m = 0.0f;
#pragma unroll
        for (int w = 0; w < WT; ++w) {
            float acc = (float)((double)tot[w] * FIXR);  // exact int64->double, pow-2, 1 rounding
            float v = fmaxf(__fadd_rn(__fmul_rn(acc, sc), bv), 0.0f);
            g_fbuf[((size_t)(b * O + o) * H + h) * W + w0 + w] = v;
            m = fmaxf(m, v);
        }
#pragma unroll
        for (int off = 16; off; off >>= 1) m = fmaxf(m, __shfl_xor_sync(0xffffffffu, m, off));
        if ((lane_o & 31) == 0) atomicMax(&g_maxi[oslot], __float_as_int(m));
    }
}

// ------- LUT fc: fixed-point int accumulation, OT x NC -------
template <int F, int OT, int NC, bool RELU>
__global__ void __launch_bounds__(OT * NC) k_fc(const float* __restrict__ lut,
                                                const float* __restrict__ bias, float* out_ext,
                                                int woff, int O, int aslot, int wslot, int oslot) {
    __shared__ int slut_i[256];
    __shared__ __align__(16) unsigned short sia[F];
    __shared__ s64 sred[(NC > 1 ? (NC - 1) * OT : 1)];
    const int lx = threadIdx.x, cc = threadIdx.y;
    const int tid = lx + OT * cc;
    constexpr int NT = OT * NC;
    const int b = blockIdx.y;
    for (int i = tid; i < 256; i += NT)
        slut_i[i] = __float2int_rn(__fmul_rn(lut[i], FIXS));
    for (int f = tid; f < F; f += NT)
        sia[f] = (unsigned short)((unsigned int)g_qa[b * F + f] << 6);
    __syncthreads();

    const int o = blockIdx.x * OT + lx;
    const uchar4* wq = reinterpret_cast<const uchar4*>(g_qw + woff) + o;
    const char* lb = reinterpret_cast<const char*>(slut_i);
    constexpr int F4C = F / 4 / NC;
    s64 t0 = 0, t1 = 0, t2 = 0, t3 = 0;
    for (int jj = 0; jj < F4C / 8; ++jj) {
        int p0 = 0, p1 = 0, p2 = 0, p3 = 0;  // 8 taps each, max 8*66*2^21 = 1.1e9
#pragma unroll
        for (int j2 = 0; j2 < 8; ++j2) {
            int f4 = cc * F4C + jj * 8 + j2;
            uchar4 wv = wq[(size_t)f4 * O];
            ushort4 iv = *reinterpret_cast<const ushort4*>(&sia[f4 * 4]);
            p0 += *reinterpret_cast<const int*>(lb + (iv.x + (unsigned int)wv.x));
            p1 += *reinterpret_cast<const int*>(lb + (iv.y + (unsigned int)wv.y));
            p2 += *reinterpret_cast<const int*>(lb + (iv.z + (unsigned int)wv.z));
            p3 += *reinterpret_cast<const int*>(lb + (iv.w + (unsigned int)wv.w));
        }
        t0 += (s64)p0; t1 += (s64)p1; t2 += (s64)p2; t3 += (s64)p3;
    }
    s64 total = (t0 + t1) + (t2 + t3);  // exact

    if (NC > 1) {
        if (cc > 0) sred[(cc - 1) * OT + lx] = total;
        __syncthreads();
        if (cc == 0) {
#pragma unroll
            for (int i = 0; i < NC - 1; ++i) total += sred[i * OT + lx];
        }
    }

    if (cc == 0) {
        float acc = (float)((double)total * FIXR);
        float sc = __fmul_rn(slot_scale(aslot), slot_scale(wslot));
        float v = __fadd_rn(__fmul_rn(acc, sc), bias[o]);
        if (RELU) {
            v = fmaxf(v, 0.0f);
            g_fbuf[(size_t)b * O + o] = v;
            float m = v;
#pragma unroll
            for (int off = 16; off; off >>= 1) m = fmaxf(m, __shfl_xor_sync(0xffffffffu, m, off));
            if ((lx & 31) == 0) atomicMax(&g_maxi[oslot], __float_as_int(m));
        } else {
            out_ext[(size_t)b * O + o] = v;
        }
    }
}

// ------- tiny fc7: warp per output, exact int64 butterfly -------
__global__ void __launch_bounds__(320) k_fc_small(const float* __restrict__ lut,
                                                  const float* __restrict__ bias, float* out,
                                                  int woff, int aslot, int wslot) {
    __shared__ int slut_i[256];
    __shared__ __align__(16) unsigned short sia[4096];
    const int lane = threadIdx.x, o = threadIdx.y, b = blockIdx.x;
    const int tid = lane + 32 * o;
    for (int i = tid; i < 256; i += 320)
        slut_i[i] = __float2int_rn(__fmul_rn(lut[i], FIXS));
    for (int f = tid; f < 4096; f += 320)
        sia[f] = (unsigned short)((unsigned int)g_qa[b * 4096 + f] << 6);
    __syncthreads();

    const uchar4* wq = reinterpret_cast<const uchar4*>(g_qw + woff) + o;
    const char* lb = reinterpret_cast<const char*>(slut_i);
    s64 tot = 0;
    int p = 0;
#pragma unroll 4
    for (int j = 0; j < 32; ++j) {
        int f4 = j * 32 + lane;
        uchar4 wv = wq[f4 * 10];
        ushort4 iv = *reinterpret_cast<const ushort4*>(&sia[f4 * 4]);
        p += *reinterpret_cast<const int*>(lb + (iv.x + (unsigned int)wv.x));
        p += *reinterpret_cast<const int*>(lb + (iv.y + (unsigned int)wv.y));
        p += *reinterpret_cast<const int*>(lb + (iv.z + (unsigned int)wv.z));
        p += *reinterpret_cast<const int*>(lb + (iv.w + (unsigned int)wv.w));
        if ((j & 1) == 1) { tot += (s64)p; p = 0; }  // 8 taps per widen
    }
#pragma unroll
    for (int off = 16; off; off >>= 1)
        tot += __shfl_xor_sync(0xffffffffu, tot, off);  // exact 64-bit butterfly
    if (lane == 0) {
        float acc = (float)((double)tot * FIXR);
        float sc = __fmul_rn(slot_scale(aslot), slot_scale(wslot));
        out[b * 10 + o] = __fadd_rn(__fmul_rn(acc, sc), bias[o]);
    }
}

extern "C" void kernel_launch(void* const* d_in, const int* in_sizes, int n_in,
                              void* d_out, int out_size) {
    const float* x = (const float*)d_in[0];
    const float* w[8]; const float* bb[8];
    for (int i = 0; i < 8; i++) { w[i] = (const float*)d_in[1 + 2 * i]; bb[i] = (const float*)d_in[2 + 2 * i]; }
    const float* luts = (const float*)d_in[17];
    float* out = (float*)d_out;

    k_init<<<1, 16>>>();

    AMaxArgs am;
    int wn[8] = {1728, 110592, 663552, 884736, 589824, 16777216, 16777216, 40960};
    am.b0[0] = 0;
    for (int i = 0; i < 8; i++) {
        am.p[i] = w[i]; am.n[i] = wn[i]; am.slot[i] = i;
        int bl = wn[i] / 8192; if (bl < 1) bl = 1; if (bl > 864) bl = 864;
        am.b0[i + 1] = am.b0[i] + bl;
    }
    am.p[8] = x; am.n[8] = 24576; am.slot[8] = 8;
    am.b0[9] = am.b0[8] + 3;
    k_absmax_all<<<am.b0[9], 256>>>(am);

    QWCArgs qc; for (int i = 0; i < 5; i++) qc.w[i] = w[i];
    k_qw_conv<<<(750144 + 255) / 256, 256>>>(qc);

    k_conv<3, 64, 32, 32, 8, 64, 1, true><<<dim3(1, 4, 256), dim3(64, 1)>>>(
        luts + 0 * 256, bb[0], x, W0OFF, 8, 0, 9);
    k_pool_quant<<<512, 256>>>(64, 32, 32, 9);
    k_conv<64, 192, 16, 16, 8, 64, 4, false><<<dim3(3, 2, 128), dim3(64, 4)>>>(
        luts + 1 * 256, bb[1], nullptr, W1OFF, 9, 1, 10);
    k_pool_quant<<<384, 256>>>(192, 16, 16, 10);
    k_conv<192, 384, 8, 8, 8, 64, 8, false><<<dim3(6, 1, 64), dim3(64, 8)>>>(
        luts + 2 * 256, bb[2], nullptr, W2OFF, 10, 2, 11);
    k_quant_act<<<768, 256>>>(nullptr, 384, 8, 8, 11);
    k_conv<384, 256, 8, 8, 8, 32, 8, false><<<dim3(8, 1, 64), dim3(32, 8)>>>(
        luts + 3 * 256, bb[3], nullptr, W3OFF, 11, 3, 12);
    k_quant_act<<<512, 256>>>(nullptr, 256, 8, 8, 12);
    k_conv<256, 256, 8, 8, 8, 32, 8, false><<<dim3(8, 1, 64), dim3(32, 8)>>>(
        luts + 4 * 256, bb[4], nullptr, W4OFF, 12, 4, 13);
    k_pool_quant_fc<<<128, 256>>>(13);

    QWFArgs qf; qf.w[0] = w[5]; qf.w[1] = w[6]; qf.w[2] = w[7];
    k_qw_fc<<<dim3(32, 128, 3), 256>>>(qf);

    k_fc<4096, 128, 8, true><<<dim3(32, 8), dim3(128, 8)>>>(luts + 5 * 256, bb[5], nullptr, W5OFF, 4096, 13, 5, 14);
    k_quant_act_fc<<<128, 256>>>(14);
    k_fc<4096, 128, 8, true><<<dim3(32, 8), dim3(128, 8)>>>(luts + 6 * 256, bb[6], nullptr, W6OFF, 4096, 14, 6, 15);
    k_quant_act_fc<<<128, 256>>>(15);
    k_fc_small<<<8, dim3(32, 10)>>>(luts + 7 * 256, bb[7], out, W7OFF, 15, 7);
}